// round 5
// baseline (speedup 1.0000x reference)
#include <cuda_runtime.h>

#define L_ 6
#define B_ 512
#define N_ 65
#define C_ 768
#define H_ 12
#define D_ 64
#define LAT_ 256
#define BN_ (B_*N_)          /* 33280 */

/* ---------------- scratch (static device globals; no runtime alloc) -------- */
__device__ float g_x  [(size_t)BN_ * C_];
__device__ float g_h  [(size_t)BN_ * C_];
__device__ float g_qkv[(size_t)BN_ * 3 * C_];
__device__ float g_bs [(size_t)B_ * H_ * 65 * 65];
__device__ float g_o  [(size_t)BN_ * C_];
__device__ float g_c1 [(size_t)B_ * 2 * LAT_];
__device__ float g_c2 [(size_t)B_ * H_ * LAT_];
__device__ float g_mlp[(size_t)BN_ * 4 * C_];

/* ---------------- tf32 helpers -------------------------------------------- */
__device__ __forceinline__ unsigned f2tf(float x) {
    unsigned u; asm("cvt.rna.tf32.f32 %0, %1;" : "=r"(u) : "f"(x)); return u;
}

/* ---------------- GEMM: C = A(MxK,row,lda) * B(KxN,row,ldb) ---------------
   EPI : 0 plain, 1 +aux (residual), 2 *silu(aux) (gated MLP, in-place OK)
   BVEC: true  -> ldb%4==0 AND Nn%128==0 (vector B loads, no col guards)
         false -> scalar guarded B loads (bias GEMM, ldb=4225)
   Requirements: M % 128 == 0, K % 16 == 0, lda % 4 == 0.
   Pipeline: prefetch next k-tile into registers before the MMA phase.      */
template<int EPI, bool BVEC>
__global__ void __launch_bounds__(256, 2) gemm_tf32(
    const float* __restrict__ A, int lda,
    const float* __restrict__ Bg, int ldb,
    float* __restrict__ Og, int ldc,
    const float* __restrict__ aux,
    int M, int Nn, int K)
{
    __shared__ unsigned As[128][17];
    __shared__ unsigned Bs[16][132];
    const int tid  = threadIdx.x;
    const int lane = tid & 31, warp = tid >> 5;
    const int wm = (warp & 1) * 64, wn = (warp >> 1) * 32;
    const int gr = lane >> 2, gc = lane & 3;
    const int mBase = blockIdx.y * 128;
    const int nBase = blockIdx.x * 128;

    /* per-thread load coordinates (fixed across k-tiles) */
    const int ar0 = tid >> 2,          ak0 = (tid & 3) * 4;          /* A vec */
    const int ar1 = (tid + 256) >> 2,  ak1 = ((tid + 256) & 3) * 4;
    const int bk0 = tid >> 5,          bc0 = (tid & 31) * 4;         /* B vec */
    const int bk1 = (tid + 256) >> 5,  bc1 = ((tid + 256) & 31) * 4;

    float4 aR[2];
    float4 bR[2];
    float  bS[8];

    auto loadA = [&](int kt) {
        aR[0] = *(const float4*)&A[(size_t)(mBase + ar0) * lda + kt + ak0];
        aR[1] = *(const float4*)&A[(size_t)(mBase + ar1) * lda + kt + ak1];
    };
    auto loadB = [&](int kt) {
        if (BVEC) {
            bR[0] = *(const float4*)&Bg[(size_t)(kt + bk0) * ldb + nBase + bc0];
            bR[1] = *(const float4*)&Bg[(size_t)(kt + bk1) * ldb + nBase + bc1];
        } else {
            #pragma unroll
            for (int i = 0; i < 8; i++) {
                int u = tid + i * 256;
                int kk = u >> 7, cc = u & 127;
                int col = nBase + cc;
                bS[i] = (col < Nn) ? Bg[(size_t)(kt + kk) * ldb + col] : 0.f;
            }
        }
    };
    auto stage = [&]() {
        As[ar0][ak0]     = f2tf(aR[0].x); As[ar0][ak0 + 1] = f2tf(aR[0].y);
        As[ar0][ak0 + 2] = f2tf(aR[0].z); As[ar0][ak0 + 3] = f2tf(aR[0].w);
        As[ar1][ak1]     = f2tf(aR[1].x); As[ar1][ak1 + 1] = f2tf(aR[1].y);
        As[ar1][ak1 + 2] = f2tf(aR[1].z); As[ar1][ak1 + 3] = f2tf(aR[1].w);
        if (BVEC) {
            Bs[bk0][bc0]     = f2tf(bR[0].x); Bs[bk0][bc0 + 1] = f2tf(bR[0].y);
            Bs[bk0][bc0 + 2] = f2tf(bR[0].z); Bs[bk0][bc0 + 3] = f2tf(bR[0].w);
            Bs[bk1][bc1]     = f2tf(bR[1].x); Bs[bk1][bc1 + 1] = f2tf(bR[1].y);
            Bs[bk1][bc1 + 2] = f2tf(bR[1].z); Bs[bk1][bc1 + 3] = f2tf(bR[1].w);
        } else {
            #pragma unroll
            for (int i = 0; i < 8; i++) {
                int u = tid + i * 256;
                Bs[u >> 7][u & 127] = f2tf(bS[i]);
            }
        }
    };

    float acc[4][4][4];
    #pragma unroll
    for (int a = 0; a < 4; a++)
        #pragma unroll
        for (int b = 0; b < 4; b++)
            #pragma unroll
            for (int c = 0; c < 4; c++) acc[a][b][c] = 0.f;

    loadA(0); loadB(0);                       /* prologue prefetch */

    for (int kt = 0; kt < K; kt += 16) {
        stage();
        __syncthreads();
        if (kt + 16 < K) { loadA(kt + 16); loadB(kt + 16); }  /* overlap w/ MMA */
        #pragma unroll
        for (int ks = 0; ks < 2; ks++) {
            const int k0 = ks * 8;
            unsigned bf0[4], bf1[4];
            #pragma unroll
            for (int nt = 0; nt < 4; nt++) {
                int col = wn + nt * 8 + gr;
                bf0[nt] = Bs[k0 + gc][col];
                bf1[nt] = Bs[k0 + gc + 4][col];
            }
            #pragma unroll
            for (int mt = 0; mt < 4; mt++) {
                int r = wm + mt * 16 + gr;
                unsigned a0 = As[r][k0 + gc],     a1 = As[r + 8][k0 + gc];
                unsigned a2 = As[r][k0 + gc + 4], a3 = As[r + 8][k0 + gc + 4];
                #pragma unroll
                for (int nt = 0; nt < 4; nt++) {
                    asm volatile(
                        "mma.sync.aligned.m16n8k8.row.col.f32.tf32.tf32.f32 "
                        "{%0,%1,%2,%3}, {%4,%5,%6,%7}, {%8,%9}, {%0,%1,%2,%3};\n"
                        : "+f"(acc[mt][nt][0]), "+f"(acc[mt][nt][1]),
                          "+f"(acc[mt][nt][2]), "+f"(acc[mt][nt][3])
                        : "r"(a0), "r"(a1), "r"(a2), "r"(a3),
                          "r"(bf0[nt]), "r"(bf1[nt]));
                }
            }
        }
        __syncthreads();
    }
    /* epilogue */
    #pragma unroll
    for (int mt = 0; mt < 4; mt++)
        #pragma unroll
        for (int nt = 0; nt < 4; nt++) {
            int row0 = mBase + wm + mt * 16 + gr;
            int col0 = nBase + wn + nt * 8 + gc * 2;
            #pragma unroll
            for (int e = 0; e < 4; e++) {
                int row = row0 + (e >> 1) * 8;
                int col = col0 + (e & 1);
                if (BVEC || col < Nn) {
                    size_t idx = (size_t)row * ldc + col;
                    float v = acc[mt][nt][e];
                    if (EPI == 1) v += aux[idx];
                    else if (EPI == 2) { float g = aux[idx]; v *= g / (1.f + expf(-g)); }
                    Og[idx] = v;
                }
            }
        }
}

/* ---------------- LayerNorm (one block per row) ---------------------------- */
template<bool SILU>
__global__ void __launch_bounds__(256) ln_kernel(
    const float* __restrict__ in, float* __restrict__ out,
    const float* __restrict__ g, const float* __restrict__ b, int W)
{
    const int row = blockIdx.x;
    const float* x = in + (size_t)row * W;
    float* y = out + (size_t)row * W;
    float s = 0.f, ss = 0.f;
    for (int i = threadIdx.x; i < W; i += 256) { float v = x[i]; s += v; ss += v * v; }
    int lane = threadIdx.x & 31, wid = threadIdx.x >> 5;
    #pragma unroll
    for (int o = 16; o; o >>= 1) {
        s  += __shfl_xor_sync(~0u, s, o);
        ss += __shfl_xor_sync(~0u, ss, o);
    }
    __shared__ float sh0[8], sh1[8];
    if (lane == 0) { sh0[wid] = s; sh1[wid] = ss; }
    __syncthreads();
    if (threadIdx.x == 0) {
        float a = 0.f, c = 0.f;
        for (int i = 0; i < 8; i++) { a += sh0[i]; c += sh1[i]; }
        sh0[0] = a; sh1[0] = c;
    }
    __syncthreads();
    float mean = sh0[0] / W;
    float inv  = rsqrtf(sh1[0] / W - mean * mean + 1e-5f);
    for (int i = threadIdx.x; i < W; i += 256) {
        float v = (x[i] - mean) * inv * g[i] + b[i];
        if (SILU) v = v / (1.f + expf(-v));
        y[i] = v;
    }
}

/* ---------------- per-head Q/K LayerNorm (warp per (b,n,h)) ---------------- */
__global__ void __launch_bounds__(256) qkln_kernel(
    float* __restrict__ qkv,
    const float* __restrict__ qg, const float* __restrict__ qb,
    const float* __restrict__ kg, const float* __restrict__ kb)
{
    int w = blockIdx.x * 8 + (threadIdx.x >> 5);
    if (w >= BN_ * H_) return;
    int lane = threadIdx.x & 31;
    int bn = w / H_, h = w % H_;
    #pragma unroll
    for (int sel = 0; sel < 2; sel++) {
        float* p = qkv + ((size_t)bn * 3 + sel) * C_ + h * D_;
        float v0 = p[lane], v1 = p[lane + 32];
        float s = v0 + v1, ss = v0 * v0 + v1 * v1;
        #pragma unroll
        for (int o = 16; o; o >>= 1) {
            s  += __shfl_xor_sync(~0u, s, o);
            ss += __shfl_xor_sync(~0u, ss, o);
        }
        float mean = s * (1.f / 64.f);
        float inv  = rsqrtf(ss * (1.f / 64.f) - mean * mean + 1e-5f);
        const float* gg = sel ? kg : qg;
        const float* bb = sel ? kb : qb;
        float sc = sel ? 1.f : 0.125f;   /* DH^-0.5 applied to q only */
        p[lane]      = ((v0 - mean) * inv * gg[lane]      + bb[lane])      * sc;
        p[lane + 32] = ((v1 - mean) * inv * gg[lane + 32] + bb[lane + 32]) * sc;
    }
}

/* ---------------- fused attention: S=QK^T+bias, softmax, O=SV -------------- */
#define ATTN_SMEM ((3 * 65 * 64 + 68 * 66) * 4)

__device__ __forceinline__ float dot4(float4 a, float4 b) {
    return a.x * b.x + a.y * b.y + a.z * b.z + a.w * b.w;
}

__global__ void __launch_bounds__(256) attn_kernel(
    const float* __restrict__ qkv, const float* __restrict__ bias,
    float* __restrict__ o)
{
    extern __shared__ float sm[];
    float* Qs = sm;                  /* 65*64 */
    float* Ks = Qs + 65 * 64;
    float* Vs = Ks + 65 * 64;
    float* S  = Vs + 65 * 64;        /* [68][66] padded */
    const int bh = blockIdx.x;
    const int b = bh / H_, h = bh % H_;
    const float* base = qkv + (size_t)b * N_ * 3 * C_ + h * D_;
    for (int i = threadIdx.x; i < 65 * 64; i += 256) {
        int n = i >> 6, d = i & 63;
        size_t off = (size_t)n * 3 * C_ + d;
        Qs[i] = base[off];
        Ks[i] = base[off + C_];
        Vs[i] = base[off + 2 * C_];
    }
    __syncthreads();

    /* S = Q K^T + bias : 4x4 register tiles over a 17x17 tile grid */
    const float* bp = bias + (size_t)bh * 65 * 65;
    const float4* Q4 = (const float4*)Qs;
    const float4* K4 = (const float4*)Ks;
    for (int t = threadIdx.x; t < 17 * 17; t += 256) {
        int n0 = (t / 17) * 4, m0 = (t % 17) * 4;
        float acc[4][4] = {};
        #pragma unroll 4
        for (int d4 = 0; d4 < 16; d4++) {
            float4 qv[4], kv[4];
            #pragma unroll
            for (int i = 0; i < 4; i++) qv[i] = Q4[(n0 + i) * 16 + d4];
            #pragma unroll
            for (int j = 0; j < 4; j++) kv[j] = K4[(m0 + j) * 16 + d4];
            #pragma unroll
            for (int i = 0; i < 4; i++)
                #pragma unroll
                for (int j = 0; j < 4; j++) acc[i][j] += dot4(qv[i], kv[j]);
        }
        #pragma unroll
        for (int i = 0; i < 4; i++)
            #pragma unroll
            for (int j = 0; j < 4; j++) {
                int n = n0 + i, m = m0 + j;
                if (n < 65 && m < 65) S[n * 66 + m] = acc[i][j] + bp[n * 65 + m];
            }
    }
    __syncthreads();

    /* softmax per row (warp per row) */
    int lane = threadIdx.x & 31, wid = threadIdx.x >> 5;
    for (int n = wid; n < 65; n += 8) {
        float* r = S + n * 66;
        float mx = -1e30f;
        for (int m = lane; m < 65; m += 32) mx = fmaxf(mx, r[m]);
        #pragma unroll
        for (int ofs = 16; ofs; ofs >>= 1) mx = fmaxf(mx, __shfl_xor_sync(~0u, mx, ofs));
        float sum = 0.f;
        for (int m = lane; m < 65; m += 32) { float e = __expf(r[m] - mx); r[m] = e; sum += e; }
        #pragma unroll
        for (int ofs = 16; ofs; ofs >>= 1) sum += __shfl_xor_sync(~0u, sum, ofs);
        float inv = 1.f / sum;
        for (int m = lane; m < 65; m += 32) r[m] *= inv;
    }
    __syncthreads();

    /* O = S V : 4x4 register tiles over a 17x16 tile grid, write (B,N,H,D) */
    for (int t = threadIdx.x; t < 17 * 16; t += 256) {
        int n0 = (t / 16) * 4, d0 = (t % 16) * 4;
        float acc[4][4] = {};
        for (int m = 0; m < 65; m++) {
            float4 vv = *(const float4*)&Vs[m * 64 + d0];
            float sa[4];
            #pragma unroll
            for (int i = 0; i < 4; i++) sa[i] = S[(n0 + i) * 66 + m];
            #pragma unroll
            for (int i = 0; i < 4; i++) {
                acc[i][0] += sa[i] * vv.x; acc[i][1] += sa[i] * vv.y;
                acc[i][2] += sa[i] * vv.z; acc[i][3] += sa[i] * vv.w;
            }
        }
        #pragma unroll
        for (int i = 0; i < 4; i++)
            if (n0 + i < 65) {
                float* op = o + (size_t)(b * N_ + n0 + i) * C_ + h * D_ + d0;
                op[0] = acc[i][0]; op[1] = acc[i][1];
                op[2] = acc[i][2]; op[3] = acc[i][3];
            }
    }
}

/* ---------------- host orchestration -------------------------------------- */
extern "C" void kernel_launch(void* const* d_in, const int* in_sizes, int n_in,
                              void* d_out, int out_size)
{
    (void)in_sizes; (void)n_in; (void)out_size;
    const float* x_in   = (const float*)d_in[0];
    const float* ln1_g  = (const float*)d_in[1];
    const float* ln1_b  = (const float*)d_in[2];
    const float* qkv_w  = (const float*)d_in[3];
    const float* proj_w = (const float*)d_in[4];
    const float* qn_g   = (const float*)d_in[5];
    const float* qn_b   = (const float*)d_in[6];
    const float* kn_g   = (const float*)d_in[7];
    const float* kn_b   = (const float*)d_in[8];
    const float* sg_w1  = (const float*)d_in[9];
    const float* sg1_g  = (const float*)d_in[10];
    const float* sg1_b  = (const float*)d_in[11];
    const float* sg_w2  = (const float*)d_in[12];
    const float* sg2_g  = (const float*)d_in[13];
    const float* sg2_b  = (const float*)d_in[14];
    const float* sgbw   = (const float*)d_in[15];
    const float* ln2_g  = (const float*)d_in[16];
    const float* ln2_b  = (const float*)d_in[17];
    const float* gate_w = (const float*)d_in[18];
    const float* val_w  = (const float*)d_in[19];
    const float* out_w  = (const float*)d_in[20];

    float *X, *Hh, *QKV, *BIAS, *O, *C1, *C2, *MLP;
    cudaGetSymbolAddress((void**)&X,    g_x);
    cudaGetSymbolAddress((void**)&Hh,   g_h);
    cudaGetSymbolAddress((void**)&QKV,  g_qkv);
    cudaGetSymbolAddress((void**)&BIAS, g_bs);
    cudaGetSymbolAddress((void**)&O,    g_o);
    cudaGetSymbolAddress((void**)&C1,   g_c1);
    cudaGetSymbolAddress((void**)&C2,   g_c2);
    cudaGetSymbolAddress((void**)&MLP,  g_mlp);

    cudaFuncSetAttribute(attn_kernel,
                         cudaFuncAttributeMaxDynamicSharedMemorySize, ATTN_SMEM);

    for (int l = 0; l < L_; l++) {
        /* layer 0 reads the harness input directly; later layers read scratch */
        const float* Xin = (l == 0) ? x_in : X;

        /* h = LN1(x) */
        ln_kernel<false><<<BN_, 256>>>(Xin, Hh, ln1_g + l * C_, ln1_b + l * C_, C_);
        /* qkv = h @ qkv_w */
        gemm_tf32<0, true><<<dim3(18, 260), 256>>>(Hh, C_,
            qkv_w + (size_t)l * C_ * 3 * C_, 3 * C_, QKV, 3 * C_, nullptr,
            BN_, 3 * C_, C_);
        /* per-head q/k LN (+q scale) in-place */
        qkln_kernel<<<(BN_ * H_) / 8, 256>>>(QKV,
            qn_g + l * D_, qn_b + l * D_, kn_g + l * D_, kn_b + l * D_);
        /* CLS bias MLP: cls rows are h[b*N + 0] (lda = N*C) */
        gemm_tf32<0, true><<<dim3(4, 4), 256>>>(Hh, N_ * C_,
            sg_w1 + (size_t)l * C_ * 2 * LAT_, 2 * LAT_, C1, 2 * LAT_, nullptr,
            B_, 2 * LAT_, C_);
        ln_kernel<true><<<B_, 256>>>(C1, C1,
            sg1_g + l * 2 * LAT_, sg1_b + l * 2 * LAT_, 2 * LAT_);
        gemm_tf32<0, true><<<dim3(24, 4), 256>>>(C1, 2 * LAT_,
            sg_w2 + (size_t)l * 2 * LAT_ * H_ * LAT_, H_ * LAT_, C2, H_ * LAT_,
            nullptr, B_, H_ * LAT_, 2 * LAT_);
        ln_kernel<false><<<B_, 256>>>(C2, C2,
            sg2_g + l * H_ * LAT_, sg2_b + l * H_ * LAT_, H_ * LAT_);
        /* bias = lat2 @ bw : (B*H x 256) @ (256 x 4225), ldb odd -> scalar B */
        gemm_tf32<0, false><<<dim3(34, 48), 256>>>(C2, LAT_,
            sgbw + (size_t)l * LAT_ * 4225, 4225, BIAS, 4225, nullptr,
            B_ * H_, 4225, LAT_);
        /* fused attention */
        attn_kernel<<<B_ * H_, 256, ATTN_SMEM>>>(QKV, BIAS, O);
        /* x = x_in/x + o @ proj_w  (writes scratch X) */
        gemm_tf32<1, true><<<dim3(6, 260), 256>>>(O, C_,
            proj_w + (size_t)l * C_ * C_, C_, X, C_, Xin, BN_, C_, C_);
        /* h2 = LN2(x) */
        ln_kernel<false><<<BN_, 256>>>(X, Hh, ln2_g + l * C_, ln2_b + l * C_, C_);
        /* mlp = h2 @ vw ; then mlp = (h2 @ gw) * silu(mlp) in-place */
        gemm_tf32<0, true><<<dim3(24, 260), 256>>>(Hh, C_,
            val_w + (size_t)l * C_ * 4 * C_, 4 * C_, MLP, 4 * C_, nullptr,
            BN_, 4 * C_, C_);
        gemm_tf32<2, true><<<dim3(24, 260), 256>>>(Hh, C_,
            gate_w + (size_t)l * C_ * 4 * C_, 4 * C_, MLP, 4 * C_, MLP,
            BN_, 4 * C_, C_);
        /* x = x + mlp @ ow  (last layer writes straight to d_out) */
        float* xo = (l == L_ - 1) ? (float*)d_out : X;
        gemm_tf32<1, true><<<dim3(6, 260), 256>>>(MLP, 4 * C_,
            out_w + (size_t)l * 4 * C_ * C_, C_, xo, C_, X, BN_, C_, 4 * C_);
    }
}

// round 9
// speedup vs baseline: 1.2382x; 1.2382x over previous
#include <cuda_runtime.h>

#define L_ 6
#define B_ 512
#define N_ 65
#define C_ 768
#define H_ 12
#define D_ 64
#define LAT_ 256
#define BN_ (B_*N_)          /* 33280 */

/* ---------------- scratch (static device globals; no runtime alloc) -------- */
__device__ float g_x  [(size_t)BN_ * C_];
__device__ float g_h  [(size_t)BN_ * C_];
__device__ float g_qkv[(size_t)BN_ * 3 * C_];
__device__ float g_bs [(size_t)B_ * H_ * 65 * 65];
__device__ float g_o  [(size_t)BN_ * C_];
__device__ float g_c1 [(size_t)B_ * 2 * LAT_];
__device__ float g_c2 [(size_t)B_ * H_ * LAT_];
__device__ float g_mlp[(size_t)BN_ * 4 * C_];

/* ---------------- tf32 helpers -------------------------------------------- */
__device__ __forceinline__ unsigned f2tf(float x) {
    unsigned u; asm("cvt.rna.tf32.f32 %0, %1;" : "=r"(u) : "f"(x)); return u;
}

/* ---------------- GEMM: C = A(MxK,row,lda) * B(KxN,row,ldb) ---------------
   EPI : 0 plain, 1 +aux (residual), 2 *silu(aux) (gated MLP, in-place OK)
   BVEC: true  -> ldb%4==0 AND Nn%128==0 (vector B loads, no col guards)
         false -> scalar guarded B loads (bias GEMM, ldb=4225)
   Requirements: M % 128 == 0, K % 16 == 0, lda % 4 == 0.
   Conflict-free smem: A stride 20 (banks 20*gr+gc all distinct mod 32),
                       B stride 136 (banks 8*gc+gr all distinct mod 32).
   Double-buffered smem, one barrier per k-tile; global prefetch in regs.   */
#define APAD 20
#define BPAD 136
template<int EPI, bool BVEC>
__global__ void __launch_bounds__(256, 2) gemm_tf32(
    const float* __restrict__ A, int lda,
    const float* __restrict__ Bg, int ldb,
    float* __restrict__ Og, int ldc,
    const float* __restrict__ aux,
    int M, int Nn, int K)
{
    __shared__ unsigned As[2][128][APAD];
    __shared__ unsigned Bs[2][16][BPAD];
    const int tid  = threadIdx.x;
    const int lane = tid & 31, warp = tid >> 5;
    const int wm = (warp & 1) * 64, wn = (warp >> 1) * 32;
    const int gr = lane >> 2, gc = lane & 3;
    const int mBase = blockIdx.y * 128;
    const int nBase = blockIdx.x * 128;

    /* per-thread load coordinates (fixed across k-tiles) */
    const int ar0 = tid >> 2,          ak0 = (tid & 3) * 4;          /* A vec */
    const int ar1 = (tid + 256) >> 2,  ak1 = ((tid + 256) & 3) * 4;
    const int bk0 = tid >> 5,          bc0 = (tid & 31) * 4;         /* B vec */
    const int bk1 = (tid + 256) >> 5,  bc1 = ((tid + 256) & 31) * 4;

    float4 aR[2];
    float4 bR[2];
    float  bS[8];

    auto loadA = [&](int kt) {
        aR[0] = *(const float4*)&A[(size_t)(mBase + ar0) * lda + kt + ak0];
        aR[1] = *(const float4*)&A[(size_t)(mBase + ar1) * lda + kt + ak1];
    };
    auto loadB = [&](int kt) {
        if (BVEC) {
            bR[0] = *(const float4*)&Bg[(size_t)(kt + bk0) * ldb + nBase + bc0];
            bR[1] = *(const float4*)&Bg[(size_t)(kt + bk1) * ldb + nBase + bc1];
        } else {
            #pragma unroll
            for (int i = 0; i < 8; i++) {
                int u = tid + i * 256;
                int kk = u >> 7, cc = u & 127;
                int col = nBase + cc;
                bS[i] = (col < Nn) ? Bg[(size_t)(kt + kk) * ldb + col] : 0.f;
            }
        }
    };
    auto stage = [&](int buf) {
        As[buf][ar0][ak0]     = f2tf(aR[0].x); As[buf][ar0][ak0 + 1] = f2tf(aR[0].y);
        As[buf][ar0][ak0 + 2] = f2tf(aR[0].z); As[buf][ar0][ak0 + 3] = f2tf(aR[0].w);
        As[buf][ar1][ak1]     = f2tf(aR[1].x); As[buf][ar1][ak1 + 1] = f2tf(aR[1].y);
        As[buf][ar1][ak1 + 2] = f2tf(aR[1].z); As[buf][ar1][ak1 + 3] = f2tf(aR[1].w);
        if (BVEC) {
            Bs[buf][bk0][bc0]     = f2tf(bR[0].x); Bs[buf][bk0][bc0 + 1] = f2tf(bR[0].y);
            Bs[buf][bk0][bc0 + 2] = f2tf(bR[0].z); Bs[buf][bk0][bc0 + 3] = f2tf(bR[0].w);
            Bs[buf][bk1][bc1]     = f2tf(bR[1].x); Bs[buf][bk1][bc1 + 1] = f2tf(bR[1].y);
            Bs[buf][bk1][bc1 + 2] = f2tf(bR[1].z); Bs[buf][bk1][bc1 + 3] = f2tf(bR[1].w);
        } else {
            #pragma unroll
            for (int i = 0; i < 8; i++) {
                int u = tid + i * 256;
                Bs[buf][u >> 7][u & 127] = f2tf(bS[i]);
            }
        }
    };

    float acc[4][4][4];
    #pragma unroll
    for (int a = 0; a < 4; a++)
        #pragma unroll
        for (int b = 0; b < 4; b++)
            #pragma unroll
            for (int c = 0; c < 4; c++) acc[a][b][c] = 0.f;

    loadA(0); loadB(0);                 /* prologue prefetch */
    stage(0);
    __syncthreads();

    int cur = 0;
    for (int kt = 0; kt < K; kt += 16) {
        const bool hasNext = (kt + 16) < K;
        if (hasNext) { loadA(kt + 16); loadB(kt + 16); }  /* LDG overlaps MMA */

        const unsigned (* __restrict__ Ac)[APAD] = As[cur];
        const unsigned (* __restrict__ Bc)[BPAD] = Bs[cur];
        #pragma unroll
        for (int ks = 0; ks < 2; ks++) {
            const int k0 = ks * 8;
            unsigned bf0[4], bf1[4];
            #pragma unroll
            for (int nt = 0; nt < 4; nt++) {
                int col = wn + nt * 8 + gr;
                bf0[nt] = Bc[k0 + gc][col];
                bf1[nt] = Bc[k0 + gc + 4][col];
            }
            #pragma unroll
            for (int mt = 0; mt < 4; mt++) {
                int r = wm + mt * 16 + gr;
                unsigned a0 = Ac[r][k0 + gc],     a1 = Ac[r + 8][k0 + gc];
                unsigned a2 = Ac[r][k0 + gc + 4], a3 = Ac[r + 8][k0 + gc + 4];
                #pragma unroll
                for (int nt = 0; nt < 4; nt++) {
                    asm volatile(
                        "mma.sync.aligned.m16n8k8.row.col.f32.tf32.tf32.f32 "
                        "{%0,%1,%2,%3}, {%4,%5,%6,%7}, {%8,%9}, {%0,%1,%2,%3};\n"
                        : "+f"(acc[mt][nt][0]), "+f"(acc[mt][nt][1]),
                          "+f"(acc[mt][nt][2]), "+f"(acc[mt][nt][3])
                        : "r"(a0), "r"(a1), "r"(a2), "r"(a3),
                          "r"(bf0[nt]), "r"(bf1[nt]));
                }
            }
        }
        if (hasNext) stage(cur ^ 1);
        __syncthreads();
        cur ^= 1;
    }

    /* epilogue: e={0,1} and e={2,3} are column-adjacent -> float2 stores */
    #pragma unroll
    for (int mt = 0; mt < 4; mt++)
        #pragma unroll
        for (int nt = 0; nt < 4; nt++) {
            int row0 = mBase + wm + mt * 16 + gr;
            int col0 = nBase + wn + nt * 8 + gc * 2;
            #pragma unroll
            for (int half = 0; half < 2; half++) {
                int row = row0 + half * 8;
                float v0 = acc[mt][nt][half * 2];
                float v1 = acc[mt][nt][half * 2 + 1];
                if (BVEC) {
                    size_t idx = (size_t)row * ldc + col0;
                    if (EPI == 1) {
                        float2 a2v = *(const float2*)&aux[idx];
                        v0 += a2v.x; v1 += a2v.y;
                    } else if (EPI == 2) {
                        float2 a2v = *(const float2*)&aux[idx];
                        v0 *= a2v.x / (1.f + __expf(-a2v.x));
                        v1 *= a2v.y / (1.f + __expf(-a2v.y));
                    }
                    float2 o2; o2.x = v0; o2.y = v1;
                    *(float2*)&Og[idx] = o2;
                } else {
                    if (col0 < Nn)     Og[(size_t)row * ldc + col0]     = v0;
                    if (col0 + 1 < Nn) Og[(size_t)row * ldc + col0 + 1] = v1;
                }
            }
        }
}

/* ---------------- LayerNorm (one block per row) ---------------------------- */
template<bool SILU>
__global__ void __launch_bounds__(256) ln_kernel(
    const float* __restrict__ in, float* __restrict__ out,
    const float* __restrict__ g, const float* __restrict__ b, int W)
{
    const int row = blockIdx.x;
    const float* x = in + (size_t)row * W;
    float* y = out + (size_t)row * W;
    float s = 0.f, ss = 0.f;
    for (int i = threadIdx.x; i < W; i += 256) { float v = x[i]; s += v; ss += v * v; }
    int lane = threadIdx.x & 31, wid = threadIdx.x >> 5;
    #pragma unroll
    for (int o = 16; o; o >>= 1) {
        s  += __shfl_xor_sync(~0u, s, o);
        ss += __shfl_xor_sync(~0u, ss, o);
    }
    __shared__ float sh0[8], sh1[8];
    if (lane == 0) { sh0[wid] = s; sh1[wid] = ss; }
    __syncthreads();
    if (threadIdx.x == 0) {
        float a = 0.f, c = 0.f;
        for (int i = 0; i < 8; i++) { a += sh0[i]; c += sh1[i]; }
        sh0[0] = a; sh1[0] = c;
    }
    __syncthreads();
    float mean = sh0[0] / W;
    float inv  = rsqrtf(sh1[0] / W - mean * mean + 1e-5f);
    for (int i = threadIdx.x; i < W; i += 256) {
        float v = (x[i] - mean) * inv * g[i] + b[i];
        if (SILU) v = v / (1.f + __expf(-v));
        y[i] = v;
    }
}

/* ------- fused attention: per-head Q/K LN, S=QK^T+bias, softmax, O=SV ------ */
#define ATTN_SMEM ((3 * 65 * 64 + 68 * 66) * 4)

__device__ __forceinline__ float dot4(float4 a, float4 b) {
    return a.x * b.x + a.y * b.y + a.z * b.z + a.w * b.w;
}

__global__ void __launch_bounds__(256) attn_kernel(
    const float* __restrict__ qkv, const float* __restrict__ bias,
    const float* __restrict__ qg, const float* __restrict__ qb,
    const float* __restrict__ kg, const float* __restrict__ kb,
    float* __restrict__ o)
{
    extern __shared__ float sm[];
    float* Qs = sm;                  /* 65*64 */
    float* Ks = Qs + 65 * 64;
    float* Vs = Ks + 65 * 64;
    float* S  = Vs + 65 * 64;        /* [68][66] padded */
    const int bh = blockIdx.x;
    const int b = bh / H_, h = bh % H_;
    const float* base = qkv + (size_t)b * N_ * 3 * C_ + h * D_;
    for (int i = threadIdx.x; i < 65 * 64; i += 256) {
        int n = i >> 6, d = i & 63;
        size_t off = (size_t)n * 3 * C_ + d;
        Qs[i] = base[off];
        Ks[i] = base[off + C_];
        Vs[i] = base[off + 2 * C_];
    }
    __syncthreads();

    /* per-head LN on Q (then *scale) and K rows, in smem (warp per row) */
    int lane = threadIdx.x & 31, wid = threadIdx.x >> 5;
    for (int n = wid; n < 65; n += 8) {
        #pragma unroll
        for (int sel = 0; sel < 2; sel++) {
            float* p = (sel ? Ks : Qs) + n * 64;
            float v0 = p[lane], v1 = p[lane + 32];
            float s = v0 + v1, ss = v0 * v0 + v1 * v1;
            #pragma unroll
            for (int ofs = 16; ofs; ofs >>= 1) {
                s  += __shfl_xor_sync(~0u, s, ofs);
                ss += __shfl_xor_sync(~0u, ss, ofs);
            }
            float mean = s * (1.f / 64.f);
            float inv  = rsqrtf(ss * (1.f / 64.f) - mean * mean + 1e-5f);
            const float* gg = sel ? kg : qg;
            const float* bb = sel ? kb : qb;
            float sc = sel ? 1.f : 0.125f;   /* DH^-0.5 on q only */
            p[lane]      = ((v0 - mean) * inv * gg[lane]      + bb[lane])      * sc;
            p[lane + 32] = ((v1 - mean) * inv * gg[lane + 32] + bb[lane + 32]) * sc;
        }
    }
    __syncthreads();

    /* S = Q K^T + bias : 4x4 register tiles over a 17x17 tile grid */
    const float* bp = bias + (size_t)bh * 65 * 65;
    const float4* Q4 = (const float4*)Qs;
    const float4* K4 = (const float4*)Ks;
    for (int t = threadIdx.x; t < 17 * 17; t += 256) {
        int n0 = (t / 17) * 4, m0 = (t % 17) * 4;
        float acc[4][4] = {};
        #pragma unroll 4
        for (int d4 = 0; d4 < 16; d4++) {
            float4 qv[4], kv[4];
            #pragma unroll
            for (int i = 0; i < 4; i++) qv[i] = Q4[(n0 + i) * 16 + d4];
            #pragma unroll
            for (int j = 0; j < 4; j++) kv[j] = K4[(m0 + j) * 16 + d4];
            #pragma unroll
            for (int i = 0; i < 4; i++)
                #pragma unroll
                for (int j = 0; j < 4; j++) acc[i][j] += dot4(qv[i], kv[j]);
        }
        #pragma unroll
        for (int i = 0; i < 4; i++)
            #pragma unroll
            for (int j = 0; j < 4; j++) {
                int n = n0 + i, m = m0 + j;
                if (n < 65 && m < 65) S[n * 66 + m] = acc[i][j] + bp[n * 65 + m];
            }
    }
    __syncthreads();

    /* softmax per row (warp per row) */
    for (int n = wid; n < 65; n += 8) {
        float* r = S + n * 66;
        float mx = -1e30f;
        for (int m = lane; m < 65; m += 32) mx = fmaxf(mx, r[m]);
        #pragma unroll
        for (int ofs = 16; ofs; ofs >>= 1) mx = fmaxf(mx, __shfl_xor_sync(~0u, mx, ofs));
        float sum = 0.f;
        for (int m = lane; m < 65; m += 32) { float e = __expf(r[m] - mx); r[m] = e; sum += e; }
        #pragma unroll
        for (int ofs = 16; ofs; ofs >>= 1) sum += __shfl_xor_sync(~0u, sum, ofs);
        float inv = 1.f / sum;
        for (int m = lane; m < 65; m += 32) r[m] *= inv;
    }
    __syncthreads();

    /* O = S V : 4x4 register tiles over a 17x16 tile grid, write (B,N,H,D) */
    for (int t = threadIdx.x; t < 17 * 16; t += 256) {
        int n0 = (t / 16) * 4, d0 = (t % 16) * 4;
        float acc[4][4] = {};
        for (int m = 0; m < 65; m++) {
            float4 vv = *(const float4*)&Vs[m * 64 + d0];
            float sa[4];
            #pragma unroll
            for (int i = 0; i < 4; i++) sa[i] = S[(n0 + i) * 66 + m];
            #pragma unroll
            for (int i = 0; i < 4; i++) {
                acc[i][0] += sa[i] * vv.x; acc[i][1] += sa[i] * vv.y;
                acc[i][2] += sa[i] * vv.z; acc[i][3] += sa[i] * vv.w;
            }
        }
        #pragma unroll
        for (int i = 0; i < 4; i++)
            if (n0 + i < 65) {
                float* op = o + (size_t)(b * N_ + n0 + i) * C_ + h * D_ + d0;
                op[0] = acc[i][0]; op[1] = acc[i][1];
                op[2] = acc[i][2]; op[3] = acc[i][3];
            }
    }
}

/* ---------------- host orchestration -------------------------------------- */
extern "C" void kernel_launch(void* const* d_in, const int* in_sizes, int n_in,
                              void* d_out, int out_size)
{
    (void)in_sizes; (void)n_in; (void)out_size;
    const float* x_in   = (const float*)d_in[0];
    const float* ln1_g  = (const float*)d_in[1];
    const float* ln1_b  = (const float*)d_in[2];
    const float* qkv_w  = (const float*)d_in[3];
    const float* proj_w = (const float*)d_in[4];
    const float* qn_g   = (const float*)d_in[5];
    const float* qn_b   = (const float*)d_in[6];
    const float* kn_g   = (const float*)d_in[7];
    const float* kn_b   = (const float*)d_in[8];
    const float* sg_w1  = (const float*)d_in[9];
    const float* sg1_g  = (const float*)d_in[10];
    const float* sg1_b  = (const float*)d_in[11];
    const float* sg_w2  = (const float*)d_in[12];
    const float* sg2_g  = (const float*)d_in[13];
    const float* sg2_b  = (const float*)d_in[14];
    const float* sgbw   = (const float*)d_in[15];
    const float* ln2_g  = (const float*)d_in[16];
    const float* ln2_b  = (const float*)d_in[17];
    const float* gate_w = (const float*)d_in[18];
    const float* val_w  = (const float*)d_in[19];
    const float* out_w  = (const float*)d_in[20];

    float *X, *Hh, *QKV, *BIAS, *O, *C1, *C2, *MLP;
    cudaGetSymbolAddress((void**)&X,    g_x);
    cudaGetSymbolAddress((void**)&Hh,   g_h);
    cudaGetSymbolAddress((void**)&QKV,  g_qkv);
    cudaGetSymbolAddress((void**)&BIAS, g_bs);
    cudaGetSymbolAddress((void**)&O,    g_o);
    cudaGetSymbolAddress((void**)&C1,   g_c1);
    cudaGetSymbolAddress((void**)&C2,   g_c2);
    cudaGetSymbolAddress((void**)&MLP,  g_mlp);

    cudaFuncSetAttribute(attn_kernel,
                         cudaFuncAttributeMaxDynamicSharedMemorySize, ATTN_SMEM);

    for (int l = 0; l < L_; l++) {
        /* layer 0 reads the harness input directly; later layers read scratch */
        const float* Xin = (l == 0) ? x_in : X;

        /* h = LN1(x) */
        ln_kernel<false><<<BN_, 256>>>(Xin, Hh, ln1_g + l * C_, ln1_b + l * C_, C_);
        /* qkv = h @ qkv_w */
        gemm_tf32<0, true><<<dim3(18, 260), 256>>>(Hh, C_,
            qkv_w + (size_t)l * C_ * 3 * C_, 3 * C_, QKV, 3 * C_, nullptr,
            BN_, 3 * C_, C_);
        /* CLS bias MLP: cls rows are h[b*N + 0] (lda = N*C) */
        gemm_tf32<0, true><<<dim3(4, 4), 256>>>(Hh, N_ * C_,
            sg_w1 + (size_t)l * C_ * 2 * LAT_, 2 * LAT_, C1, 2 * LAT_, nullptr,
            B_, 2 * LAT_, C_);
        ln_kernel<true><<<B_, 256>>>(C1, C1,
            sg1_g + l * 2 * LAT_, sg1_b + l * 2 * LAT_, 2 * LAT_);
        gemm_tf32<0, true><<<dim3(24, 4), 256>>>(C1, 2 * LAT_,
            sg_w2 + (size_t)l * 2 * LAT_ * H_ * LAT_, H_ * LAT_, C2, H_ * LAT_,
            nullptr, B_, H_ * LAT_, 2 * LAT_);
        ln_kernel<false><<<B_, 256>>>(C2, C2,
            sg2_g + l * H_ * LAT_, sg2_b + l * H_ * LAT_, H_ * LAT_);
        /* bias = lat2 @ bw : (B*H x 256) @ (256 x 4225), ldb odd -> scalar B */
        gemm_tf32<0, false><<<dim3(34, 48), 256>>>(C2, LAT_,
            sgbw + (size_t)l * LAT_ * 4225, 4225, BIAS, 4225, nullptr,
            B_ * H_, 4225, LAT_);
        /* fused attention (per-head q/k LN + scale happen in-kernel) */
        attn_kernel<<<B_ * H_, 256, ATTN_SMEM>>>(QKV, BIAS,
            qn_g + l * D_, qn_b + l * D_, kn_g + l * D_, kn_b + l * D_, O);
        /* x = x_in/x + o @ proj_w  (writes scratch X) */
        gemm_tf32<1, true><<<dim3(6, 260), 256>>>(O, C_,
            proj_w + (size_t)l * C_ * C_, C_, X, C_, Xin, BN_, C_, C_);
        /* h2 = LN2(x) */
        ln_kernel<false><<<BN_, 256>>>(X, Hh, ln2_g + l * C_, ln2_b + l * C_, C_);
        /* mlp = h2 @ vw ; then mlp = (h2 @ gw) * silu(mlp) in-place */
        gemm_tf32<0, true><<<dim3(24, 260), 256>>>(Hh, C_,
            val_w + (size_t)l * C_ * 4 * C_, 4 * C_, MLP, 4 * C_, nullptr,
            BN_, 4 * C_, C_);
        gemm_tf32<2, true><<<dim3(24, 260), 256>>>(Hh, C_,
            gate_w + (size_t)l * C_ * 4 * C_, 4 * C_, MLP, 4 * C_, MLP,
            BN_, 4 * C_, C_);
        /* x = x + mlp @ ow  (last layer writes straight to d_out) */
        float* xo = (l == L_ - 1) ? (float*)d_out : X;
        gemm_tf32<1, true><<<dim3(6, 260), 256>>>(MLP, 4 * C_,
            out_w + (size_t)l * 4 * C_ * C_, C_, xo, C_, X, BN_, C_, 4 * C_);
    }
}

// round 14
// speedup vs baseline: 2.0376x; 1.6456x over previous
#include <cuda_runtime.h>
#include <cuda_fp16.h>
#include <cstdint>

#define L_ 6
#define B_ 512
#define N_ 65
#define C_ 768
#define H_ 12
#define D_ 64
#define LAT_ 256
#define BN_ (B_*N_)          /* 33280 */
#define BSLD 4352            /* padded bias row stride (65*65=4225 -> 34*128) */

/* ---------------- scratch (static device globals; no runtime alloc) -------- */
__device__ float  g_x   [(size_t)BN_ * C_];
__device__ __half g_hh  [(size_t)BN_ * C_];          /* LN1/LN2 out (GEMM A) */
__device__ float  g_qkv [(size_t)BN_ * 3 * C_];
__device__ float  g_bs  [(size_t)B_ * H_ * BSLD];
__device__ __half g_oh  [(size_t)BN_ * C_];          /* attn out (GEMM A)    */
__device__ float  g_c1f [(size_t)B_ * 2 * LAT_];
__device__ __half g_c1h [(size_t)B_ * 2 * LAT_];
__device__ float  g_c2f [(size_t)B_ * H_ * LAT_];
__device__ __half g_c2h [(size_t)B_ * H_ * LAT_];
__device__ float  g_mlpf[(size_t)BN_ * 4 * C_];      /* h2@vw (fp32 aux)     */
__device__ __half g_mlph[(size_t)BN_ * 4 * C_];      /* gated MLP (GEMM A)   */
/* transposed fp16 weights [N][K] (rewritten per layer, in-stream) */
__device__ __half g_qkvT [(size_t)3 * C_ * C_];
__device__ __half g_projT[(size_t)C_ * C_];
__device__ __half g_w1T  [(size_t)2 * LAT_ * C_];
__device__ __half g_w2T  [(size_t)H_ * LAT_ * 2 * LAT_];
__device__ __half g_bwT  [(size_t)BSLD * LAT_];
__device__ __half g_valT [(size_t)4 * C_ * C_];
__device__ __half g_gateT[(size_t)4 * C_ * C_];
__device__ __half g_outT [(size_t)C_ * 4 * C_];

/* ------------- weight transpose+convert: in f32[K][Nin] -> out h[Npad][K] -- */
__global__ void __launch_bounds__(256) transpose_h(
    const float* __restrict__ in, int ldin, __half* __restrict__ out,
    int K, int Nin, int Npad)
{
    __shared__ float t[32][33];
    const int tx = threadIdx.x & 31, ty = threadIdx.x >> 5;   /* 32 x 8 */
    const int nb = blockIdx.x * 32, kb = blockIdx.y * 32;
    #pragma unroll
    for (int j = 0; j < 4; j++) {
        int k = kb + ty + j * 8, n = nb + tx;
        t[ty + j * 8][tx] = (n < Nin) ? in[(size_t)k * ldin + n] : 0.f;
    }
    __syncthreads();
    #pragma unroll
    for (int j = 0; j < 4; j++) {
        int n = nb + ty + j * 8, k = kb + tx;
        if (n < Npad) out[(size_t)n * K + k] = __float2half(t[tx][ty + j * 8]);
    }
}

/* ---------------- fp16 GEMM: C = A(MxK,h) * Bt(NxK,h)^T  -------------------
   A row-major [M][K] (lda halves), Bt row-major [N][K] (ldb halves).
   128x128 CTA tile, k-tile 32, double buffered, mma.m16n8k16 f16, f32 accum.
   EPI: 0 plain f32 out; 1 +aux f32 out; 2 acc*silu(aux) half out.
   M%128==0, N%128==0, K%32==0, lda/ldb %8==0.                               */
#define PU 20   /* u32 per smem row (16 used): banks (20*gr+gc)%32 all distinct */

template<int EPI, bool OUTH>
__global__ void __launch_bounds__(256, 2) gemm_h(
    const __half* __restrict__ A, int lda,
    const __half* __restrict__ Bt, int ldb,
    void* __restrict__ Ogv, int ldc,
    const float* __restrict__ aux, int K)
{
    __shared__ uint32_t As[2][128][PU];
    __shared__ uint32_t Bs[2][128][PU];
    const int tid = threadIdx.x, lane = tid & 31, w = tid >> 5;
    const int wm = (w & 1) * 64, wn = (w >> 1) * 32;
    const int gr = lane >> 2, gc = lane & 3;
    const int mBase = blockIdx.y * 128, nBase = blockIdx.x * 128;
    const int r0 = tid >> 2,         q0 = tid & 3;          /* chunks 0..255 */
    const int r1 = (tid + 256) >> 2, q1 = (tid + 256) & 3;  /* chunks 256..511 */

    uint4 aR0, aR1, bR0, bR1;
    auto ldAB = [&](int kt) {
        aR0 = *(const uint4*)&A [(size_t)(mBase + r0) * lda + kt + q0 * 8];
        aR1 = *(const uint4*)&A [(size_t)(mBase + r1) * lda + kt + q1 * 8];
        bR0 = *(const uint4*)&Bt[(size_t)(nBase + r0) * ldb + kt + q0 * 8];
        bR1 = *(const uint4*)&Bt[(size_t)(nBase + r1) * ldb + kt + q1 * 8];
    };
    auto stage = [&](int buf) {
        *(uint4*)&As[buf][r0][q0 * 4] = aR0;
        *(uint4*)&As[buf][r1][q1 * 4] = aR1;
        *(uint4*)&Bs[buf][r0][q0 * 4] = bR0;
        *(uint4*)&Bs[buf][r1][q1 * 4] = bR1;
    };

    float acc[4][4][4];
    #pragma unroll
    for (int a = 0; a < 4; a++)
        #pragma unroll
        for (int b = 0; b < 4; b++)
            #pragma unroll
            for (int c = 0; c < 4; c++) acc[a][b][c] = 0.f;

    ldAB(0);
    stage(0);
    __syncthreads();

    for (int kt = 0; kt < K; kt += 32) {
        const int buf = (kt >> 5) & 1;
        const bool more = (kt + 32) < K;
        if (more) ldAB(kt + 32);

        const uint32_t (* __restrict__ Ac)[PU] = As[buf];
        const uint32_t (* __restrict__ Bc)[PU] = Bs[buf];
        #pragma unroll
        for (int ks = 0; ks < 2; ks++) {
            const int kb = ks * 8;
            uint32_t b0[4], b1[4];
            #pragma unroll
            for (int nt = 0; nt < 4; nt++) {
                int row = wn + nt * 8 + gr;
                b0[nt] = Bc[row][kb + gc];
                b1[nt] = Bc[row][kb + gc + 4];
            }
            #pragma unroll
            for (int mt = 0; mt < 4; mt++) {
                int r = wm + mt * 16 + gr;
                uint32_t a0 = Ac[r][kb + gc],     a1 = Ac[r + 8][kb + gc];
                uint32_t a2 = Ac[r][kb + gc + 4], a3 = Ac[r + 8][kb + gc + 4];
                #pragma unroll
                for (int nt = 0; nt < 4; nt++) {
                    asm volatile(
                        "mma.sync.aligned.m16n8k16.row.col.f32.f16.f16.f32 "
                        "{%0,%1,%2,%3}, {%4,%5,%6,%7}, {%8,%9}, {%0,%1,%2,%3};\n"
                        : "+f"(acc[mt][nt][0]), "+f"(acc[mt][nt][1]),
                          "+f"(acc[mt][nt][2]), "+f"(acc[mt][nt][3])
                        : "r"(a0), "r"(a1), "r"(a2), "r"(a3),
                          "r"(b0[nt]), "r"(b1[nt]));
                }
            }
        }
        if (more) stage(buf ^ 1);
        __syncthreads();
    }

    /* epilogue: lane owns (row0,col0..col0+1) and (row0+8, same cols) */
    #pragma unroll
    for (int mt = 0; mt < 4; mt++)
        #pragma unroll
        for (int nt = 0; nt < 4; nt++) {
            int row0 = mBase + wm + mt * 16 + gr;
            int col0 = nBase + wn + nt * 8 + gc * 2;
            #pragma unroll
            for (int half = 0; half < 2; half++) {
                int row = row0 + half * 8;
                float v0 = acc[mt][nt][half * 2];
                float v1 = acc[mt][nt][half * 2 + 1];
                size_t idx = (size_t)row * ldc + col0;
                if (EPI == 1) {
                    float2 a2v = *(const float2*)&aux[idx];
                    v0 += a2v.x; v1 += a2v.y;
                } else if (EPI == 2) {
                    float2 a2v = *(const float2*)&aux[idx];
                    v0 *= a2v.x / (1.f + __expf(-a2v.x));
                    v1 *= a2v.y / (1.f + __expf(-a2v.y));
                }
                if (OUTH) {
                    __half2 h2v = __floats2half2_rn(v0, v1);
                    *(__half2*)&((__half*)Ogv)[idx] = h2v;
                } else {
                    float2 o2; o2.x = v0; o2.y = v1;
                    *(float2*)&((float*)Ogv)[idx] = o2;
                }
            }
        }
}

/* ---------------- LayerNorm (one block per row), fp16 output --------------- */
template<bool SILU>
__global__ void __launch_bounds__(256) ln_kernel(
    const float* __restrict__ in, __half* __restrict__ out,
    const float* __restrict__ g, const float* __restrict__ b, int W)
{
    const int row = blockIdx.x;
    const float* x = in + (size_t)row * W;
    __half* y = out + (size_t)row * W;
    float s = 0.f, ss = 0.f;
    for (int i = threadIdx.x; i < W; i += 256) { float v = x[i]; s += v; ss += v * v; }
    int lane = threadIdx.x & 31, wid = threadIdx.x >> 5;
    #pragma unroll
    for (int o = 16; o; o >>= 1) {
        s  += __shfl_xor_sync(~0u, s, o);
        ss += __shfl_xor_sync(~0u, ss, o);
    }
    __shared__ float sh0[8], sh1[8];
    if (lane == 0) { sh0[wid] = s; sh1[wid] = ss; }
    __syncthreads();
    if (threadIdx.x == 0) {
        float a = 0.f, c = 0.f;
        for (int i = 0; i < 8; i++) { a += sh0[i]; c += sh1[i]; }
        sh0[0] = a; sh1[0] = c;
    }
    __syncthreads();
    float mean = sh0[0] / W;
    float inv  = rsqrtf(sh1[0] / W - mean * mean + 1e-5f);
    for (int i = threadIdx.x; i < W; i += 256) {
        float v = (x[i] - mean) * inv * g[i] + b[i];
        if (SILU) v = v / (1.f + __expf(-v));
        y[i] = __float2half(v);
    }
}

/* ------- fused attention: per-head Q/K LN, S=QK^T+bias, softmax, O=SV ------ */
#define ATTN_SMEM ((3 * 65 * 64 + 68 * 66) * 4)

__device__ __forceinline__ float dot4(float4 a, float4 b) {
    return a.x * b.x + a.y * b.y + a.z * b.z + a.w * b.w;
}

__global__ void __launch_bounds__(256) attn_kernel(
    const float* __restrict__ qkv, const float* __restrict__ bias,
    const float* __restrict__ qg, const float* __restrict__ qb,
    const float* __restrict__ kg, const float* __restrict__ kb,
    __half* __restrict__ o)
{
    extern __shared__ float sm[];
    float* Qs = sm;                  /* 65*64 */
    float* Ks = Qs + 65 * 64;
    float* Vs = Ks + 65 * 64;
    float* S  = Vs + 65 * 64;        /* [68][66] padded */
    const int bh = blockIdx.x;
    const int b = bh / H_, h = bh % H_;
    const float* base = qkv + (size_t)b * N_ * 3 * C_ + h * D_;
    for (int i = threadIdx.x; i < 65 * 64; i += 256) {
        int n = i >> 6, d = i & 63;
        size_t off = (size_t)n * 3 * C_ + d;
        Qs[i] = base[off];
        Ks[i] = base[off + C_];
        Vs[i] = base[off + 2 * C_];
    }
    __syncthreads();

    int lane = threadIdx.x & 31, wid = threadIdx.x >> 5;
    for (int n = wid; n < 65; n += 8) {
        #pragma unroll
        for (int sel = 0; sel < 2; sel++) {
            float* p = (sel ? Ks : Qs) + n * 64;
            float v0 = p[lane], v1 = p[lane + 32];
            float s = v0 + v1, ss = v0 * v0 + v1 * v1;
            #pragma unroll
            for (int ofs = 16; ofs; ofs >>= 1) {
                s  += __shfl_xor_sync(~0u, s, ofs);
                ss += __shfl_xor_sync(~0u, ss, ofs);
            }
            float mean = s * (1.f / 64.f);
            float inv  = rsqrtf(ss * (1.f / 64.f) - mean * mean + 1e-5f);
            const float* gg = sel ? kg : qg;
            const float* bb = sel ? kb : qb;
            float sc = sel ? 1.f : 0.125f;   /* DH^-0.5 on q only */
            p[lane]      = ((v0 - mean) * inv * gg[lane]      + bb[lane])      * sc;
            p[lane + 32] = ((v1 - mean) * inv * gg[lane + 32] + bb[lane + 32]) * sc;
        }
    }
    __syncthreads();

    const float* bp = bias + (size_t)bh * BSLD;
    const float4* Q4 = (const float4*)Qs;
    const float4* K4 = (const float4*)Ks;
    for (int t = threadIdx.x; t < 17 * 17; t += 256) {
        int n0 = (t / 17) * 4, m0 = (t % 17) * 4;
        float acc[4][4] = {};
        #pragma unroll 4
        for (int d4 = 0; d4 < 16; d4++) {
            float4 qv[4], kv[4];
            #pragma unroll
            for (int i = 0; i < 4; i++) qv[i] = Q4[(n0 + i) * 16 + d4];
            #pragma unroll
            for (int j = 0; j < 4; j++) kv[j] = K4[(m0 + j) * 16 + d4];
            #pragma unroll
            for (int i = 0; i < 4; i++)
                #pragma unroll
                for (int j = 0; j < 4; j++) acc[i][j] += dot4(qv[i], kv[j]);
        }
        #pragma unroll
        for (int i = 0; i < 4; i++)
            #pragma unroll
            for (int j = 0; j < 4; j++) {
                int n = n0 + i, m = m0 + j;
                if (n < 65 && m < 65) S[n * 66 + m] = acc[i][j] + bp[n * 65 + m];
            }
    }
    __syncthreads();

    for (int n = wid; n < 65; n += 8) {
        float* r = S + n * 66;
        float mx = -1e30f;
        for (int m = lane; m < 65; m += 32) mx = fmaxf(mx, r[m]);
        #pragma unroll
        for (int ofs = 16; ofs; ofs >>= 1) mx = fmaxf(mx, __shfl_xor_sync(~0u, mx, ofs));
        float sum = 0.f;
        for (int m = lane; m < 65; m += 32) { float e = __expf(r[m] - mx); r[m] = e; sum += e; }
        #pragma unroll
        for (int ofs = 16; ofs; ofs >>= 1) sum += __shfl_xor_sync(~0u, sum, ofs);
        float inv = 1.f / sum;
        for (int m = lane; m < 65; m += 32) r[m] *= inv;
    }
    __syncthreads();

    for (int t = threadIdx.x; t < 17 * 16; t += 256) {
        int n0 = (t / 16) * 4, d0 = (t % 16) * 4;
        float acc[4][4] = {};
        for (int m = 0; m < 65; m++) {
            float4 vv = *(const float4*)&Vs[m * 64 + d0];
            float sa[4];
            #pragma unroll
            for (int i = 0; i < 4; i++) sa[i] = S[(n0 + i) * 66 + m];
            #pragma unroll
            for (int i = 0; i < 4; i++) {
                acc[i][0] += sa[i] * vv.x; acc[i][1] += sa[i] * vv.y;
                acc[i][2] += sa[i] * vv.z; acc[i][3] += sa[i] * vv.w;
            }
        }
        #pragma unroll
        for (int i = 0; i < 4; i++)
            if (n0 + i < 65) {
                __half* op = o + (size_t)(b * N_ + n0 + i) * C_ + h * D_ + d0;
                *(__half2*)&op[0] = __floats2half2_rn(acc[i][0], acc[i][1]);
                *(__half2*)&op[2] = __floats2half2_rn(acc[i][2], acc[i][3]);
            }
    }
}

/* ---------------- host orchestration -------------------------------------- */
extern "C" void kernel_launch(void* const* d_in, const int* in_sizes, int n_in,
                              void* d_out, int out_size)
{
    (void)in_sizes; (void)n_in; (void)out_size;
    const float* x_in   = (const float*)d_in[0];
    const float* ln1_g  = (const float*)d_in[1];
    const float* ln1_b  = (const float*)d_in[2];
    const float* qkv_w  = (const float*)d_in[3];
    const float* proj_w = (const float*)d_in[4];
    const float* qn_g   = (const float*)d_in[5];
    const float* qn_b   = (const float*)d_in[6];
    const float* kn_g   = (const float*)d_in[7];
    const float* kn_b   = (const float*)d_in[8];
    const float* sg_w1  = (const float*)d_in[9];
    const float* sg1_g  = (const float*)d_in[10];
    const float* sg1_b  = (const float*)d_in[11];
    const float* sg_w2  = (const float*)d_in[12];
    const float* sg2_g  = (const float*)d_in[13];
    const float* sg2_b  = (const float*)d_in[14];
    const float* sgbw   = (const float*)d_in[15];
    const float* ln2_g  = (const float*)d_in[16];
    const float* ln2_b  = (const float*)d_in[17];
    const float* gate_w = (const float*)d_in[18];
    const float* val_w  = (const float*)d_in[19];
    const float* out_w  = (const float*)d_in[20];

    float *X, *QKV, *BIAS, *C1f, *C2f, *MLPf;
    __half *Hh, *Oh, *C1h, *C2h, *MLPh;
    __half *qkvT, *projT, *w1T, *w2T, *bwT, *valT, *gateT, *outT;
    cudaGetSymbolAddress((void**)&X,     g_x);
    cudaGetSymbolAddress((void**)&Hh,    g_hh);
    cudaGetSymbolAddress((void**)&QKV,   g_qkv);
    cudaGetSymbolAddress((void**)&BIAS,  g_bs);
    cudaGetSymbolAddress((void**)&Oh,    g_oh);
    cudaGetSymbolAddress((void**)&C1f,   g_c1f);
    cudaGetSymbolAddress((void**)&C1h,   g_c1h);
    cudaGetSymbolAddress((void**)&C2f,   g_c2f);
    cudaGetSymbolAddress((void**)&C2h,   g_c2h);
    cudaGetSymbolAddress((void**)&MLPf,  g_mlpf);
    cudaGetSymbolAddress((void**)&MLPh,  g_mlph);
    cudaGetSymbolAddress((void**)&qkvT,  g_qkvT);
    cudaGetSymbolAddress((void**)&projT, g_projT);
    cudaGetSymbolAddress((void**)&w1T,   g_w1T);
    cudaGetSymbolAddress((void**)&w2T,   g_w2T);
    cudaGetSymbolAddress((void**)&bwT,   g_bwT);
    cudaGetSymbolAddress((void**)&valT,  g_valT);
    cudaGetSymbolAddress((void**)&gateT, g_gateT);
    cudaGetSymbolAddress((void**)&outT,  g_outT);

    cudaFuncSetAttribute(attn_kernel,
                         cudaFuncAttributeMaxDynamicSharedMemorySize, ATTN_SMEM);

    const dim3 tb(256);
    for (int l = 0; l < L_; l++) {
        const float* Xin = (l == 0) ? x_in : X;

        /* per-layer weight transpose+convert to fp16 [N][K] */
        transpose_h<<<dim3(3 * C_ / 32, C_ / 32), tb>>>(
            qkv_w + (size_t)l * C_ * 3 * C_, 3 * C_, qkvT, C_, 3 * C_, 3 * C_);
        transpose_h<<<dim3(C_ / 32, C_ / 32), tb>>>(
            proj_w + (size_t)l * C_ * C_, C_, projT, C_, C_, C_);
        transpose_h<<<dim3(2 * LAT_ / 32, C_ / 32), tb>>>(
            sg_w1 + (size_t)l * C_ * 2 * LAT_, 2 * LAT_, w1T, C_, 2 * LAT_, 2 * LAT_);
        transpose_h<<<dim3(H_ * LAT_ / 32, 2 * LAT_ / 32), tb>>>(
            sg_w2 + (size_t)l * 2 * LAT_ * H_ * LAT_, H_ * LAT_, w2T, 2 * LAT_,
            H_ * LAT_, H_ * LAT_);
        transpose_h<<<dim3(BSLD / 32, LAT_ / 32), tb>>>(
            sgbw + (size_t)l * LAT_ * 4225, 4225, bwT, LAT_, 4225, BSLD);
        transpose_h<<<dim3(4 * C_ / 32, C_ / 32), tb>>>(
            val_w + (size_t)l * C_ * 4 * C_, 4 * C_, valT, C_, 4 * C_, 4 * C_);
        transpose_h<<<dim3(4 * C_ / 32, C_ / 32), tb>>>(
            gate_w + (size_t)l * C_ * 4 * C_, 4 * C_, gateT, C_, 4 * C_, 4 * C_);
        transpose_h<<<dim3(C_ / 32, 4 * C_ / 32), tb>>>(
            out_w + (size_t)l * 4 * C_ * C_, C_, outT, 4 * C_, C_, C_);

        /* h = LN1(x) -> fp16 */
        ln_kernel<false><<<BN_, tb>>>(Xin, Hh, ln1_g + l * C_, ln1_b + l * C_, C_);
        /* qkv = h @ qkv_w  (33280 x 2304 x 768) */
        gemm_h<0, false><<<dim3(18, 260), tb>>>(Hh, C_, qkvT, C_,
            QKV, 3 * C_, nullptr, C_);
        /* CLS MLP 1: (512 x 512 x 768), cls rows stride N*C */
        gemm_h<0, false><<<dim3(4, 4), tb>>>(Hh, N_ * C_, w1T, C_,
            C1f, 2 * LAT_, nullptr, C_);
        ln_kernel<true><<<B_, tb>>>(C1f, C1h,
            sg1_g + l * 2 * LAT_, sg1_b + l * 2 * LAT_, 2 * LAT_);
        /* CLS MLP 2: (512 x 3072 x 512) */
        gemm_h<0, false><<<dim3(24, 4), tb>>>(C1h, 2 * LAT_, w2T, 2 * LAT_,
            C2f, H_ * LAT_, nullptr, 2 * LAT_);
        ln_kernel<false><<<B_, tb>>>(C2f, C2h,
            sg2_g + l * H_ * LAT_, sg2_b + l * H_ * LAT_, H_ * LAT_);
        /* bias = lat2 @ bw : (6144 x 4352 x 256), pad zeros already in bwT */
        gemm_h<0, false><<<dim3(34, 48), tb>>>(C2h, LAT_, bwT, LAT_,
            BIAS, BSLD, nullptr, LAT_);
        /* fused attention (per-head q/k LN + scale in-kernel) -> fp16 O */
        attn_kernel<<<B_ * H_, tb, ATTN_SMEM>>>(QKV, BIAS,
            qn_g + l * D_, qn_b + l * D_, kn_g + l * D_, kn_b + l * D_, Oh);
        /* x = Xin + o @ proj_w : (33280 x 768 x 768) */
        gemm_h<1, false><<<dim3(6, 260), tb>>>(Oh, C_, projT, C_,
            X, C_, Xin, C_);
        /* h2 = LN2(x) -> fp16 */
        ln_kernel<false><<<BN_, tb>>>(X, Hh, ln2_g + l * C_, ln2_b + l * C_, C_);
        /* v = h2 @ vw (fp32); gated = (h2 @ gw) * silu(v) -> fp16 */
        gemm_h<0, false><<<dim3(24, 260), tb>>>(Hh, C_, valT, C_,
            MLPf, 4 * C_, nullptr, C_);
        gemm_h<2, true><<<dim3(24, 260), tb>>>(Hh, C_, gateT, C_,
            MLPh, 4 * C_, MLPf, C_);
        /* x = x + gated @ ow : (33280 x 768 x 3072), last layer -> d_out */
        float* xo = (l == L_ - 1) ? (float*)d_out : X;
        gemm_h<1, false><<<dim3(6, 260), tb>>>(MLPh, 4 * C_, outT, 4 * C_,
            xo, C_, X, 4 * C_);
    }
}

// round 15
// speedup vs baseline: 2.1296x; 1.0451x over previous
#include <cuda_runtime.h>
#include <cuda_fp16.h>
#include <cstdint>

#define L_ 6
#define B_ 512
#define N_ 65
#define C_ 768
#define H_ 12
#define D_ 64
#define LAT_ 256
#define BN_ (B_*N_)          /* 33280 */
#define BSLD 4352            /* padded bias row stride (65*65=4225 -> 34*128) */

/* ---------------- scratch (static device globals; no runtime alloc) -------- */
__device__ float  g_x   [(size_t)BN_ * C_];
__device__ __half g_hh  [(size_t)BN_ * C_];
__device__ float  g_qkv [(size_t)BN_ * 3 * C_];
__device__ float  g_bs  [(size_t)B_ * H_ * BSLD];
__device__ __half g_oh  [(size_t)BN_ * C_];
__device__ float  g_c1f [(size_t)B_ * 2 * LAT_];
__device__ __half g_c1h [(size_t)B_ * 2 * LAT_];
__device__ float  g_c2f [(size_t)B_ * H_ * LAT_];
__device__ __half g_c2h [(size_t)B_ * H_ * LAT_];
__device__ float  g_mlpf[(size_t)BN_ * 4 * C_];
__device__ __half g_mlph[(size_t)BN_ * 4 * C_];
/* transposed fp16 weights [N][K] (rewritten per layer, in-stream) */
__device__ __half g_qkvT [(size_t)3 * C_ * C_];
__device__ __half g_projT[(size_t)C_ * C_];
__device__ __half g_w1T  [(size_t)2 * LAT_ * C_];
__device__ __half g_w2T  [(size_t)H_ * LAT_ * 2 * LAT_];
__device__ __half g_bwT  [(size_t)BSLD * LAT_];
__device__ __half g_valT [(size_t)4 * C_ * C_];
__device__ __half g_gateT[(size_t)4 * C_ * C_];
__device__ __half g_outT [(size_t)C_ * 4 * C_];

__device__ __forceinline__ uint32_t smem_u32(const void* p) {
    uint32_t a;
    asm("{ .reg .u64 t; cvta.to.shared.u64 t, %1; cvt.u32.u64 %0, t; }"
        : "=r"(a) : "l"(p));
    return a;
}
#define LDSM_X4(r0, r1, r2, r3, addr) \
    asm volatile("ldmatrix.sync.aligned.m8n8.x4.shared.b16 {%0,%1,%2,%3}, [%4];" \
        : "=r"(r0), "=r"(r1), "=r"(r2), "=r"(r3) : "r"(addr))

/* ------------- weight transpose+convert: in f32[K][Nin] -> out h[Npad][K] -- */
__global__ void __launch_bounds__(256) transpose_h(
    const float* __restrict__ in, int ldin, __half* __restrict__ out,
    int K, int Nin, int Npad)
{
    __shared__ float t[32][33];
    const int tx = threadIdx.x & 31, ty = threadIdx.x >> 5;   /* 32 x 8 */
    const int nb = blockIdx.x * 32, kb = blockIdx.y * 32;
    #pragma unroll
    for (int j = 0; j < 4; j++) {
        int k = kb + ty + j * 8, n = nb + tx;
        t[ty + j * 8][tx] = (n < Nin) ? in[(size_t)k * ldin + n] : 0.f;
    }
    __syncthreads();
    #pragma unroll
    for (int j = 0; j < 4; j++) {
        int n = nb + ty + j * 8, k = kb + tx;
        if (n < Npad) out[(size_t)n * K + k] = __float2half(t[tx][ty + j * 8]);
    }
}

/* ---------------- fp16 GEMM: C = A(MxK,h) * Bt(NxK,h)^T  -------------------
   128x128 CTA tile, k-tile 32, double buffer, ldmatrix operand feed,
   mma.m16n8k16 f16 -> f32.  EPI: 0 plain f32; 1 +aux f32; 2 acc*silu(aux) h.
   M%128==0, N%128==0, K%32==0, lda/ldb %8==0.                               */
#define PU 20   /* u32/row: rows at 80B -> LDS & LDSM both conflict-free      */

template<int EPI, bool OUTH>
__global__ void __launch_bounds__(256, 2) gemm_h(
    const __half* __restrict__ A, int lda,
    const __half* __restrict__ Bt, int ldb,
    void* __restrict__ Ogv, int ldc,
    const float* __restrict__ aux, int K)
{
    __shared__ __align__(16) uint32_t As[2][128][PU];
    __shared__ __align__(16) uint32_t Bs[2][128][PU];
    const int tid = threadIdx.x, lane = tid & 31, w = tid >> 5;
    const int wm = (w & 1) * 64, wn = (w >> 1) * 32;
    const int gr = lane >> 2, gc = lane & 3;
    const int mBase = blockIdx.y * 128, nBase = blockIdx.x * 128;
    const int r0 = tid >> 2,         q0 = tid & 3;
    const int r1 = (tid + 256) >> 2, q1 = (tid + 256) & 3;

    /* ldmatrix lane base addresses (per buffer) */
    uint32_t aLB[2], bLB[2];
    {
        const uint32_t aoff = (uint32_t)(wm + (lane & 15)) * (PU * 4)
                            + ((lane >> 4) << 4);
        const uint32_t boff = (uint32_t)(wn + ((lane >> 4) << 3) + (lane & 7))
                            * (PU * 4) + (((lane >> 3) & 1) << 4);
        aLB[0] = smem_u32(&As[0][0][0]) + aoff;
        aLB[1] = smem_u32(&As[1][0][0]) + aoff;
        bLB[0] = smem_u32(&Bs[0][0][0]) + boff;
        bLB[1] = smem_u32(&Bs[1][0][0]) + boff;
    }

    uint4 aR0, aR1, bR0, bR1;
    auto ldAB = [&](int kt) {
        aR0 = *(const uint4*)&A [(size_t)(mBase + r0) * lda + kt + q0 * 8];
        aR1 = *(const uint4*)&A [(size_t)(mBase + r1) * lda + kt + q1 * 8];
        bR0 = *(const uint4*)&Bt[(size_t)(nBase + r0) * ldb + kt + q0 * 8];
        bR1 = *(const uint4*)&Bt[(size_t)(nBase + r1) * ldb + kt + q1 * 8];
    };
    auto stage = [&](int buf) {
        *(uint4*)&As[buf][r0][q0 * 4] = aR0;
        *(uint4*)&As[buf][r1][q1 * 4] = aR1;
        *(uint4*)&Bs[buf][r0][q0 * 4] = bR0;
        *(uint4*)&Bs[buf][r1][q1 * 4] = bR1;
    };

    float acc[4][4][4];
    #pragma unroll
    for (int a = 0; a < 4; a++)
        #pragma unroll
        for (int b = 0; b < 4; b++)
            #pragma unroll
            for (int c = 0; c < 4; c++) acc[a][b][c] = 0.f;

    ldAB(0);
    stage(0);
    __syncthreads();

    for (int kt = 0; kt < K; kt += 32) {
        const int buf = (kt >> 5) & 1;
        const bool more = (kt + 32) < K;
        if (more) ldAB(kt + 32);

        #pragma unroll
        for (int ks = 0; ks < 2; ks++) {
            const uint32_t kso = (uint32_t)ks * 32;   /* 16 halves = 32B */
            uint32_t bf[8];
            LDSM_X4(bf[0], bf[1], bf[2], bf[3], bLB[buf] + kso);
            LDSM_X4(bf[4], bf[5], bf[6], bf[7], bLB[buf] + kso + 16 * PU * 4);
            #pragma unroll
            for (int mt = 0; mt < 4; mt++) {
                uint32_t a0, a1, a2, a3;
                LDSM_X4(a0, a1, a2, a3, aLB[buf] + (uint32_t)mt * (16 * PU * 4) + kso);
                #pragma unroll
                for (int nt = 0; nt < 4; nt++) {
                    asm volatile(
                        "mma.sync.aligned.m16n8k16.row.col.f32.f16.f16.f32 "
                        "{%0,%1,%2,%3}, {%4,%5,%6,%7}, {%8,%9}, {%0,%1,%2,%3};\n"
                        : "+f"(acc[mt][nt][0]), "+f"(acc[mt][nt][1]),
                          "+f"(acc[mt][nt][2]), "+f"(acc[mt][nt][3])
                        : "r"(a0), "r"(a1), "r"(a2), "r"(a3),
                          "r"(bf[nt * 2]), "r"(bf[nt * 2 + 1]));
                }
            }
        }
        if (more) stage(buf ^ 1);
        __syncthreads();
    }

    /* epilogue */
    #pragma unroll
    for (int mt = 0; mt < 4; mt++)
        #pragma unroll
        for (int nt = 0; nt < 4; nt++) {
            int row0 = mBase + wm + mt * 16 + gr;
            int col0 = nBase + wn + nt * 8 + gc * 2;
            #pragma unroll
            for (int half = 0; half < 2; half++) {
                int row = row0 + half * 8;
                float v0 = acc[mt][nt][half * 2];
                float v1 = acc[mt][nt][half * 2 + 1];
                size_t idx = (size_t)row * ldc + col0;
                if (EPI == 1) {
                    float2 a2v = *(const float2*)&aux[idx];
                    v0 += a2v.x; v1 += a2v.y;
                } else if (EPI == 2) {
                    float2 a2v = *(const float2*)&aux[idx];
                    v0 *= a2v.x / (1.f + __expf(-a2v.x));
                    v1 *= a2v.y / (1.f + __expf(-a2v.y));
                }
                if (OUTH) {
                    __half2 h2v = __floats2half2_rn(v0, v1);
                    *(__half2*)&((__half*)Ogv)[idx] = h2v;
                } else {
                    float2 o2; o2.x = v0; o2.y = v1;
                    *(float2*)&((float*)Ogv)[idx] = o2;
                }
            }
        }
}

/* ---------------- LayerNorm (one block per row), fp16 output --------------- */
template<bool SILU>
__global__ void __launch_bounds__(256) ln_kernel(
    const float* __restrict__ in, __half* __restrict__ out,
    const float* __restrict__ g, const float* __restrict__ b, int W)
{
    const int row = blockIdx.x;
    const float* x = in + (size_t)row * W;
    __half* y = out + (size_t)row * W;
    float s = 0.f, ss = 0.f;
    for (int i = threadIdx.x; i < W; i += 256) { float v = x[i]; s += v; ss += v * v; }
    int lane = threadIdx.x & 31, wid = threadIdx.x >> 5;
    #pragma unroll
    for (int o = 16; o; o >>= 1) {
        s  += __shfl_xor_sync(~0u, s, o);
        ss += __shfl_xor_sync(~0u, ss, o);
    }
    __shared__ float sh0[8], sh1[8];
    if (lane == 0) { sh0[wid] = s; sh1[wid] = ss; }
    __syncthreads();
    if (threadIdx.x == 0) {
        float a = 0.f, c = 0.f;
        for (int i = 0; i < 8; i++) { a += sh0[i]; c += sh1[i]; }
        sh0[0] = a; sh1[0] = c;
    }
    __syncthreads();
    float mean = sh0[0] / W;
    float inv  = rsqrtf(sh1[0] / W - mean * mean + 1e-5f);
    for (int i = threadIdx.x; i < W; i += 256) {
        float v = (x[i] - mean) * inv * g[i] + b[i];
        if (SILU) v = v / (1.f + __expf(-v));
        y[i] = __float2half(v);
    }
}

/* ------- fused attention: per-head Q/K LN, S=QK^T+bias, softmax, O=SV ------ */
#define ATTN_SMEM ((3 * 65 * 64 + 68 * 66) * 4)

__device__ __forceinline__ float dot4(float4 a, float4 b) {
    return a.x * b.x + a.y * b.y + a.z * b.z + a.w * b.w;
}

__global__ void __launch_bounds__(256) attn_kernel(
    const float* __restrict__ qkv, const float* __restrict__ bias,
    const float* __restrict__ qg, const float* __restrict__ qb,
    const float* __restrict__ kg, const float* __restrict__ kb,
    __half* __restrict__ o)
{
    extern __shared__ float sm[];
    float* Qs = sm;
    float* Ks = Qs + 65 * 64;
    float* Vs = Ks + 65 * 64;
    float* S  = Vs + 65 * 64;        /* [68][66] padded */
    const int bh = blockIdx.x;
    const int b = bh / H_, h = bh % H_;
    const float* base = qkv + (size_t)b * N_ * 3 * C_ + h * D_;
    for (int i = threadIdx.x; i < 65 * 64; i += 256) {
        int n = i >> 6, d = i & 63;
        size_t off = (size_t)n * 3 * C_ + d;
        Qs[i] = base[off];
        Ks[i] = base[off + C_];
        Vs[i] = base[off + 2 * C_];
    }
    __syncthreads();

    int lane = threadIdx.x & 31, wid = threadIdx.x >> 5;
    for (int n = wid; n < 65; n += 8) {
        #pragma unroll
        for (int sel = 0; sel < 2; sel++) {
            float* p = (sel ? Ks : Qs) + n * 64;
            float v0 = p[lane], v1 = p[lane + 32];
            float s = v0 + v1, ss = v0 * v0 + v1 * v1;
            #pragma unroll
            for (int ofs = 16; ofs; ofs >>= 1) {
                s  += __shfl_xor_sync(~0u, s, ofs);
                ss += __shfl_xor_sync(~0u, ss, ofs);
            }
            float mean = s * (1.f / 64.f);
            float inv  = rsqrtf(ss * (1.f / 64.f) - mean * mean + 1e-5f);
            const float* gg = sel ? kg : qg;
            const float* bb = sel ? kb : qb;
            float sc = sel ? 1.f : 0.125f;
            p[lane]      = ((v0 - mean) * inv * gg[lane]      + bb[lane])      * sc;
            p[lane + 32] = ((v1 - mean) * inv * gg[lane + 32] + bb[lane + 32]) * sc;
        }
    }
    __syncthreads();

    const float* bp = bias + (size_t)bh * BSLD;
    const float4* Q4 = (const float4*)Qs;
    const float4* K4 = (const float4*)Ks;
    for (int t = threadIdx.x; t < 17 * 17; t += 256) {
        int n0 = (t / 17) * 4, m0 = (t % 17) * 4;
        float acc[4][4] = {};
        #pragma unroll 4
        for (int d4 = 0; d4 < 16; d4++) {
            float4 qv[4], kv[4];
            #pragma unroll
            for (int i = 0; i < 4; i++) qv[i] = Q4[(n0 + i) * 16 + d4];
            #pragma unroll
            for (int j = 0; j < 4; j++) kv[j] = K4[(m0 + j) * 16 + d4];
            #pragma unroll
            for (int i = 0; i < 4; i++)
                #pragma unroll
                for (int j = 0; j < 4; j++) acc[i][j] += dot4(qv[i], kv[j]);
        }
        #pragma unroll
        for (int i = 0; i < 4; i++)
            #pragma unroll
            for (int j = 0; j < 4; j++) {
                int n = n0 + i, m = m0 + j;
                if (n < 65 && m < 65) S[n * 66 + m] = acc[i][j] + bp[n * 65 + m];
            }
    }
    __syncthreads();

    for (int n = wid; n < 65; n += 8) {
        float* r = S + n * 66;
        float mx = -1e30f;
        for (int m = lane; m < 65; m += 32) mx = fmaxf(mx, r[m]);
        #pragma unroll
        for (int ofs = 16; ofs; ofs >>= 1) mx = fmaxf(mx, __shfl_xor_sync(~0u, mx, ofs));
        float sum = 0.f;
        for (int m = lane; m < 65; m += 32) { float e = __expf(r[m] - mx); r[m] = e; sum += e; }
        #pragma unroll
        for (int ofs = 16; ofs; ofs >>= 1) sum += __shfl_xor_sync(~0u, sum, ofs);
        float inv = 1.f / sum;
        for (int m = lane; m < 65; m += 32) r[m] *= inv;
    }
    __syncthreads();

    for (int t = threadIdx.x; t < 17 * 16; t += 256) {
        int n0 = (t / 16) * 4, d0 = (t % 16) * 4;
        float acc[4][4] = {};
        for (int m = 0; m < 65; m++) {
            float4 vv = *(const float4*)&Vs[m * 64 + d0];
            float sa[4];
            #pragma unroll
            for (int i = 0; i < 4; i++) sa[i] = S[(n0 + i) * 66 + m];
            #pragma unroll
            for (int i = 0; i < 4; i++) {
                acc[i][0] += sa[i] * vv.x; acc[i][1] += sa[i] * vv.y;
                acc[i][2] += sa[i] * vv.z; acc[i][3] += sa[i] * vv.w;
            }
        }
        #pragma unroll
        for (int i = 0; i < 4; i++)
            if (n0 + i < 65) {
                __half* op = o + (size_t)(b * N_ + n0 + i) * C_ + h * D_ + d0;
                *(__half2*)&op[0] = __floats2half2_rn(acc[i][0], acc[i][1]);
                *(__half2*)&op[2] = __floats2half2_rn(acc[i][2], acc[i][3]);
            }
    }
}

/* ---------------- host orchestration -------------------------------------- */
extern "C" void kernel_launch(void* const* d_in, const int* in_sizes, int n_in,
                              void* d_out, int out_size)
{
    (void)in_sizes; (void)n_in; (void)out_size;
    const float* x_in   = (const float*)d_in[0];
    const float* ln1_g  = (const float*)d_in[1];
    const float* ln1_b  = (const float*)d_in[2];
    const float* qkv_w  = (const float*)d_in[3];
    const float* proj_w = (const float*)d_in[4];
    const float* qn_g   = (const float*)d_in[5];
    const float* qn_b   = (const float*)d_in[6];
    const float* kn_g   = (const float*)d_in[7];
    const float* kn_b   = (const float*)d_in[8];
    const float* sg_w1  = (const float*)d_in[9];
    const float* sg1_g  = (const float*)d_in[10];
    const float* sg1_b  = (const float*)d_in[11];
    const float* sg_w2  = (const float*)d_in[12];
    const float* sg2_g  = (const float*)d_in[13];
    const float* sg2_b  = (const float*)d_in[14];
    const float* sgbw   = (const float*)d_in[15];
    const float* ln2_g  = (const float*)d_in[16];
    const float* ln2_b  = (const float*)d_in[17];
    const float* gate_w = (const float*)d_in[18];
    const float* val_w  = (const float*)d_in[19];
    const float* out_w  = (const float*)d_in[20];

    float *X, *QKV, *BIAS, *C1f, *C2f, *MLPf;
    __half *Hh, *Oh, *C1h, *C2h, *MLPh;
    __half *qkvT, *projT, *w1T, *w2T, *bwT, *valT, *gateT, *outT;
    cudaGetSymbolAddress((void**)&X,     g_x);
    cudaGetSymbolAddress((void**)&Hh,    g_hh);
    cudaGetSymbolAddress((void**)&QKV,   g_qkv);
    cudaGetSymbolAddress((void**)&BIAS,  g_bs);
    cudaGetSymbolAddress((void**)&Oh,    g_oh);
    cudaGetSymbolAddress((void**)&C1f,   g_c1f);
    cudaGetSymbolAddress((void**)&C1h,   g_c1h);
    cudaGetSymbolAddress((void**)&C2f,   g_c2f);
    cudaGetSymbolAddress((void**)&C2h,   g_c2h);
    cudaGetSymbolAddress((void**)&MLPf,  g_mlpf);
    cudaGetSymbolAddress((void**)&MLPh,  g_mlph);
    cudaGetSymbolAddress((void**)&qkvT,  g_qkvT);
    cudaGetSymbolAddress((void**)&projT, g_projT);
    cudaGetSymbolAddress((void**)&w1T,   g_w1T);
    cudaGetSymbolAddress((void**)&w2T,   g_w2T);
    cudaGetSymbolAddress((void**)&bwT,   g_bwT);
    cudaGetSymbolAddress((void**)&valT,  g_valT);
    cudaGetSymbolAddress((void**)&gateT, g_gateT);
    cudaGetSymbolAddress((void**)&outT,  g_outT);

    cudaFuncSetAttribute(attn_kernel,
                         cudaFuncAttributeMaxDynamicSharedMemorySize, ATTN_SMEM);

    const dim3 tb(256);
    for (int l = 0; l < L_; l++) {
        const float* Xin = (l == 0) ? x_in : X;

        /* launches ordered so overall launch #6 (ncu -s 5) = QKV GEMM */
        transpose_h<<<dim3(3 * C_ / 32, C_ / 32), tb>>>(
            qkv_w + (size_t)l * C_ * 3 * C_, 3 * C_, qkvT, C_, 3 * C_, 3 * C_);
        ln_kernel<false><<<BN_, tb>>>(Xin, Hh, ln1_g + l * C_, ln1_b + l * C_, C_);
        transpose_h<<<dim3(2 * LAT_ / 32, C_ / 32), tb>>>(
            sg_w1 + (size_t)l * C_ * 2 * LAT_, 2 * LAT_, w1T, C_, 2 * LAT_, 2 * LAT_);
        transpose_h<<<dim3(H_ * LAT_ / 32, 2 * LAT_ / 32), tb>>>(
            sg_w2 + (size_t)l * 2 * LAT_ * H_ * LAT_, H_ * LAT_, w2T, 2 * LAT_,
            H_ * LAT_, H_ * LAT_);
        transpose_h<<<dim3(BSLD / 32, LAT_ / 32), tb>>>(
            sgbw + (size_t)l * LAT_ * 4225, 4225, bwT, LAT_, 4225, BSLD);
        /* qkv = h @ qkv_w  (33280 x 2304 x 768) -- profiled launch */
        gemm_h<0, false><<<dim3(18, 260), tb>>>(Hh, C_, qkvT, C_,
            QKV, 3 * C_, nullptr, C_);
        /* CLS MLP 1: (512 x 512 x 768), cls rows stride N*C */
        gemm_h<0, false><<<dim3(4, 4), tb>>>(Hh, N_ * C_, w1T, C_,
            C1f, 2 * LAT_, nullptr, C_);
        ln_kernel<true><<<B_, tb>>>(C1f, C1h,
            sg1_g + l * 2 * LAT_, sg1_b + l * 2 * LAT_, 2 * LAT_);
        /* CLS MLP 2: (512 x 3072 x 512) */
        gemm_h<0, false><<<dim3(24, 4), tb>>>(C1h, 2 * LAT_, w2T, 2 * LAT_,
            C2f, H_ * LAT_, nullptr, 2 * LAT_);
        ln_kernel<false><<<B_, tb>>>(C2f, C2h,
            sg2_g + l * H_ * LAT_, sg2_b + l * H_ * LAT_, H_ * LAT_);
        /* bias = lat2 @ bw : (6144 x 4352 x 256) */
        gemm_h<0, false><<<dim3(34, 48), tb>>>(C2h, LAT_, bwT, LAT_,
            BIAS, BSLD, nullptr, LAT_);
        /* fused attention -> fp16 O */
        attn_kernel<<<B_ * H_, tb, ATTN_SMEM>>>(QKV, BIAS,
            qn_g + l * D_, qn_b + l * D_, kn_g + l * D_, kn_b + l * D_, Oh);
        transpose_h<<<dim3(C_ / 32, C_ / 32), tb>>>(
            proj_w + (size_t)l * C_ * C_, C_, projT, C_, C_, C_);
        /* x = Xin + o @ proj_w : (33280 x 768 x 768) */
        gemm_h<1, false><<<dim3(6, 260), tb>>>(Oh, C_, projT, C_,
            X, C_, Xin, C_);
        ln_kernel<false><<<BN_, tb>>>(X, Hh, ln2_g + l * C_, ln2_b + l * C_, C_);
        transpose_h<<<dim3(4 * C_ / 32, C_ / 32), tb>>>(
            val_w + (size_t)l * C_ * 4 * C_, 4 * C_, valT, C_, 4 * C_, 4 * C_);
        /* v = h2 @ vw (fp32) */
        gemm_h<0, false><<<dim3(24, 260), tb>>>(Hh, C_, valT, C_,
            MLPf, 4 * C_, nullptr, C_);
        transpose_h<<<dim3(4 * C_ / 32, C_ / 32), tb>>>(
            gate_w + (size_t)l * C_ * 4 * C_, 4 * C_, gateT, C_, 4 * C_, 4 * C_);
        /* gated = (h2 @ gw) * silu(v) -> fp16 */
        gemm_h<2, true><<<dim3(24, 260), tb>>>(Hh, C_, gateT, C_,
            MLPh, 4 * C_, MLPf, C_);
        transpose_h<<<dim3(C_ / 32, 4 * C_ / 32), tb>>>(
            out_w + (size_t)l * 4 * C_ * C_, C_, outT, 4 * C_, C_, C_);
        /* x = x + gated @ ow : (33280 x 768 x 3072), last layer -> d_out */
        float* xo = (l == L_ - 1) ? (float*)d_out : X;
        gemm_h<1, false><<<dim3(6, 260), tb>>>(MLPh, 4 * C_, outT, 4 * C_,
            xo, C_, X, 4 * C_);
    }
}

// round 16
// speedup vs baseline: 2.3969x; 1.1255x over previous
#include <cuda_runtime.h>
#include <cuda_fp16.h>
#include <cstdint>

#define L_ 6
#define B_ 512
#define N_ 65
#define C_ 768
#define H_ 12
#define D_ 64
#define LAT_ 256
#define BN_ (B_*N_)          /* 33280 */
#define BSLD 4352            /* padded bias row stride (65*65=4225 -> 34*128) */

/* ---------------- scratch (static device globals; no runtime alloc) -------- */
__device__ float  g_x   [(size_t)BN_ * C_];
__device__ __half g_hh  [(size_t)BN_ * C_];
__device__ __half g_qkvh[(size_t)BN_ * 3 * C_];
__device__ __half g_bsh [(size_t)B_ * H_ * BSLD];
__device__ __half g_oh  [(size_t)BN_ * C_];
__device__ float  g_c1f [(size_t)B_ * 2 * LAT_];
__device__ __half g_c1h [(size_t)B_ * 2 * LAT_];
__device__ float  g_c2f [(size_t)B_ * H_ * LAT_];
__device__ __half g_c2h [(size_t)B_ * H_ * LAT_];
__device__ __half g_mlpvh[(size_t)BN_ * 4 * C_];    /* h2@vw (silu aux, h)  */
__device__ __half g_mlph [(size_t)BN_ * 4 * C_];    /* gated MLP (GEMM A)   */
/* transposed fp16 weights [N][K] (rewritten per layer, in-stream) */
__device__ __half g_qkvT [(size_t)3 * C_ * C_];
__device__ __half g_projT[(size_t)C_ * C_];
__device__ __half g_w1T  [(size_t)2 * LAT_ * C_];
__device__ __half g_w2T  [(size_t)H_ * LAT_ * 2 * LAT_];
__device__ __half g_bwT  [(size_t)BSLD * LAT_];
__device__ __half g_valT [(size_t)4 * C_ * C_];
__device__ __half g_gateT[(size_t)4 * C_ * C_];
__device__ __half g_outT [(size_t)C_ * 4 * C_];

__device__ __forceinline__ uint32_t smem_u32(const void* p) {
    uint32_t a;
    asm("{ .reg .u64 t; cvta.to.shared.u64 t, %1; cvt.u32.u64 %0, t; }"
        : "=r"(a) : "l"(p));
    return a;
}
#define LDSM_X4(r0, r1, r2, r3, addr) \
    asm volatile("ldmatrix.sync.aligned.m8n8.x4.shared.b16 {%0,%1,%2,%3}, [%4];" \
        : "=r"(r0), "=r"(r1), "=r"(r2), "=r"(r3) : "r"(addr))
__device__ __forceinline__ void cp16(uint32_t dst, const void* src) {
    asm volatile("cp.async.cg.shared.global [%0], [%1], 16;"
                 :: "r"(dst), "l"(src) : "memory");
}
#define CP_COMMIT() asm volatile("cp.async.commit_group;" ::: "memory")
#define CP_WAIT1()  asm volatile("cp.async.wait_group 1;" ::: "memory")

/* ------------- weight transpose+convert: in f32[K][Nin] -> out h[Npad][K] -- */
__global__ void __launch_bounds__(256) transpose_h(
    const float* __restrict__ in, int ldin, __half* __restrict__ out,
    int K, int Nin, int Npad)
{
    __shared__ float t[32][33];
    const int tx = threadIdx.x & 31, ty = threadIdx.x >> 5;   /* 32 x 8 */
    const int nb = blockIdx.x * 32, kb = blockIdx.y * 32;
    #pragma unroll
    for (int j = 0; j < 4; j++) {
        int k = kb + ty + j * 8, n = nb + tx;
        t[ty + j * 8][tx] = (n < Nin) ? in[(size_t)k * ldin + n] : 0.f;
    }
    __syncthreads();
    #pragma unroll
    for (int j = 0; j < 4; j++) {
        int n = nb + ty + j * 8, k = kb + tx;
        if (n < Npad) out[(size_t)n * K + k] = __float2half(t[tx][ty + j * 8]);
    }
}

/* ---------------- fp16 GEMM: C = A(MxK,h) * Bt(NxK,h)^T  -------------------
   128x128 CTA tile, k-tile 32, 3-stage cp.async pipeline, ldmatrix feed,
   mma.m16n8k16 f16 -> f32.
   EPI: 0 plain; 1 +aux(f32); 2 acc*silu(aux).  OUTH: half out.  AUXH: half aux.
   M%128==0, N%128==0, K%32==0, lda/ldb %8==0.                               */
#define PU 20                      /* u32 per smem row (80B) — conflict-free  */
#define STG_BYTES (128 * PU * 4)   /* one matrix, one stage: 10240 B          */
#define STAGE_BYTES (2 * STG_BYTES)
#define GSMEM (3 * STAGE_BYTES)    /* 61440 B                                 */

template<int EPI, bool OUTH, bool AUXH>
__global__ void __launch_bounds__(256, 2) gemm_h(
    const __half* __restrict__ A, int lda,
    const __half* __restrict__ Bt, int ldb,
    void* __restrict__ Ogv, int ldc,
    const void* __restrict__ auxv, int K)
{
    extern __shared__ __align__(16) char dsm[];
    const uint32_t sb = smem_u32(dsm);
    const int tid = threadIdx.x, lane = tid & 31, w = tid >> 5;
    const int wm = (w & 1) * 64, wn = (w >> 1) * 32;
    const int gr = lane >> 2, gc = lane & 3;
    const int mBase = blockIdx.y * 128, nBase = blockIdx.x * 128;
    const int r0 = tid >> 2,         q0 = tid & 3;
    const int r1 = (tid + 256) >> 2, q1 = (tid + 256) & 3;
    const int T = K >> 5;

    /* per-lane ldmatrix offsets within a stage */
    const uint32_t aoff = (uint32_t)(wm + (lane & 15)) * (PU * 4)
                        + ((lane >> 4) << 4);
    const uint32_t boff = (uint32_t)(wn + ((lane >> 4) << 3) + (lane & 7))
                        * (PU * 4) + (((lane >> 3) & 1) << 4);
    /* per-thread cp.async dst offsets within a stage */
    const uint32_t dA0 = (uint32_t)(r0 * PU + q0 * 4) * 4;
    const uint32_t dA1 = (uint32_t)(r1 * PU + q1 * 4) * 4;

    auto issue = [&](int t) {
        const int kt = t << 5;
        const uint32_t stg = sb + (uint32_t)(t % 3) * STAGE_BYTES;
        cp16(stg + dA0,             &A [(size_t)(mBase + r0) * lda + kt + q0 * 8]);
        cp16(stg + dA1,             &A [(size_t)(mBase + r1) * lda + kt + q1 * 8]);
        cp16(stg + STG_BYTES + dA0, &Bt[(size_t)(nBase + r0) * ldb + kt + q0 * 8]);
        cp16(stg + STG_BYTES + dA1, &Bt[(size_t)(nBase + r1) * ldb + kt + q1 * 8]);
    };

    float acc[4][4][4];
    #pragma unroll
    for (int a = 0; a < 4; a++)
        #pragma unroll
        for (int b = 0; b < 4; b++)
            #pragma unroll
            for (int c = 0; c < 4; c++) acc[a][b][c] = 0.f;

    issue(0); CP_COMMIT();
    if (T > 1) issue(1);
    CP_COMMIT();

    for (int t = 0; t < T; t++) {
        CP_WAIT1();
        __syncthreads();
        if (t + 2 < T) issue(t + 2);
        CP_COMMIT();

        const uint32_t stg = sb + (uint32_t)(t % 3) * STAGE_BYTES;
        const uint32_t aLB = stg + aoff;
        const uint32_t bLB = stg + STG_BYTES + boff;
        #pragma unroll
        for (int ks = 0; ks < 2; ks++) {
            const uint32_t kso = (uint32_t)ks * 32;
            uint32_t bf[8];
            LDSM_X4(bf[0], bf[1], bf[2], bf[3], bLB + kso);
            LDSM_X4(bf[4], bf[5], bf[6], bf[7], bLB + kso + 16 * PU * 4);
            #pragma unroll
            for (int mt = 0; mt < 4; mt++) {
                uint32_t a0, a1, a2, a3;
                LDSM_X4(a0, a1, a2, a3, aLB + (uint32_t)mt * (16 * PU * 4) + kso);
                #pragma unroll
                for (int nt = 0; nt < 4; nt++) {
                    asm volatile(
                        "mma.sync.aligned.m16n8k16.row.col.f32.f16.f16.f32 "
                        "{%0,%1,%2,%3}, {%4,%5,%6,%7}, {%8,%9}, {%0,%1,%2,%3};\n"
                        : "+f"(acc[mt][nt][0]), "+f"(acc[mt][nt][1]),
                          "+f"(acc[mt][nt][2]), "+f"(acc[mt][nt][3])
                        : "r"(a0), "r"(a1), "r"(a2), "r"(a3),
                          "r"(bf[nt * 2]), "r"(bf[nt * 2 + 1]));
                }
            }
        }
    }

    /* epilogue */
    #pragma unroll
    for (int mt = 0; mt < 4; mt++)
        #pragma unroll
        for (int nt = 0; nt < 4; nt++) {
            int row0 = mBase + wm + mt * 16 + gr;
            int col0 = nBase + wn + nt * 8 + gc * 2;
            #pragma unroll
            for (int half = 0; half < 2; half++) {
                int row = row0 + half * 8;
                float v0 = acc[mt][nt][half * 2];
                float v1 = acc[mt][nt][half * 2 + 1];
                size_t idx = (size_t)row * ldc + col0;
                if (EPI == 1) {
                    float2 a2v = *(const float2*)&((const float*)auxv)[idx];
                    v0 += a2v.x; v1 += a2v.y;
                } else if (EPI == 2) {
                    float2 a2v;
                    if (AUXH) {
                        __half2 ah = *(const __half2*)&((const __half*)auxv)[idx];
                        a2v = __half22float2(ah);
                    } else {
                        a2v = *(const float2*)&((const float*)auxv)[idx];
                    }
                    v0 *= a2v.x / (1.f + __expf(-a2v.x));
                    v1 *= a2v.y / (1.f + __expf(-a2v.y));
                }
                if (OUTH) {
                    __half2 h2v = __floats2half2_rn(v0, v1);
                    *(__half2*)&((__half*)Ogv)[idx] = h2v;
                } else {
                    float2 o2; o2.x = v0; o2.y = v1;
                    *(float2*)&((float*)Ogv)[idx] = o2;
                }
            }
        }
}

/* ---------------- LayerNorm (one block per row), fp16 output --------------- */
template<bool SILU>
__global__ void __launch_bounds__(256) ln_kernel(
    const float* __restrict__ in, __half* __restrict__ out,
    const float* __restrict__ g, const float* __restrict__ b, int W)
{
    const int row = blockIdx.x;
    const float* x = in + (size_t)row * W;
    __half* y = out + (size_t)row * W;
    float s = 0.f, ss = 0.f;
    for (int i = threadIdx.x; i < W; i += 256) { float v = x[i]; s += v; ss += v * v; }
    int lane = threadIdx.x & 31, wid = threadIdx.x >> 5;
    #pragma unroll
    for (int o = 16; o; o >>= 1) {
        s  += __shfl_xor_sync(~0u, s, o);
        ss += __shfl_xor_sync(~0u, ss, o);
    }
    __shared__ float sh0[8], sh1[8];
    if (lane == 0) { sh0[wid] = s; sh1[wid] = ss; }
    __syncthreads();
    if (threadIdx.x == 0) {
        float a = 0.f, c = 0.f;
        for (int i = 0; i < 8; i++) { a += sh0[i]; c += sh1[i]; }
        sh0[0] = a; sh1[0] = c;
    }
    __syncthreads();
    float mean = sh0[0] / W;
    float inv  = rsqrtf(sh1[0] / W - mean * mean + 1e-5f);
    for (int i = threadIdx.x; i < W; i += 256) {
        float v = (x[i] - mean) * inv * g[i] + b[i];
        if (SILU) v = v / (1.f + __expf(-v));
        y[i] = __float2half(v);
    }
}

/* ------- fused attention: per-head Q/K LN, S=QK^T+bias, softmax, O=SV ------ */
#define ATTN_SMEM ((3 * 65 * 64 + 68 * 66) * 4)

__device__ __forceinline__ float dot4(float4 a, float4 b) {
    return a.x * b.x + a.y * b.y + a.z * b.z + a.w * b.w;
}

__global__ void __launch_bounds__(256) attn_kernel(
    const __half* __restrict__ qkv, const __half* __restrict__ bias,
    const float* __restrict__ qg, const float* __restrict__ qb,
    const float* __restrict__ kg, const float* __restrict__ kb,
    __half* __restrict__ o)
{
    extern __shared__ float sm[];
    float* Qs = sm;
    float* Ks = Qs + 65 * 64;
    float* Vs = Ks + 65 * 64;
    float* S  = Vs + 65 * 64;        /* [68][66] padded */
    const int bh = blockIdx.x;
    const int b = bh / H_, h = bh % H_;
    const __half* base = qkv + (size_t)b * N_ * 3 * C_ + h * D_;
    for (int i = threadIdx.x; i < 65 * 32; i += 256) {
        int n = i >> 5, d2 = i & 31;
        size_t off = (size_t)n * 3 * C_ + d2 * 2;
        float2 qf = __half22float2(*(const __half2*)&base[off]);
        float2 kf = __half22float2(*(const __half2*)&base[off + C_]);
        float2 vf = __half22float2(*(const __half2*)&base[off + 2 * C_]);
        Qs[n * 64 + d2 * 2] = qf.x; Qs[n * 64 + d2 * 2 + 1] = qf.y;
        Ks[n * 64 + d2 * 2] = kf.x; Ks[n * 64 + d2 * 2 + 1] = kf.y;
        Vs[n * 64 + d2 * 2] = vf.x; Vs[n * 64 + d2 * 2 + 1] = vf.y;
    }
    __syncthreads();

    int lane = threadIdx.x & 31, wid = threadIdx.x >> 5;
    for (int n = wid; n < 65; n += 8) {
        #pragma unroll
        for (int sel = 0; sel < 2; sel++) {
            float* p = (sel ? Ks : Qs) + n * 64;
            float v0 = p[lane], v1 = p[lane + 32];
            float s = v0 + v1, ss = v0 * v0 + v1 * v1;
            #pragma unroll
            for (int ofs = 16; ofs; ofs >>= 1) {
                s  += __shfl_xor_sync(~0u, s, ofs);
                ss += __shfl_xor_sync(~0u, ss, ofs);
            }
            float mean = s * (1.f / 64.f);
            float inv  = rsqrtf(ss * (1.f / 64.f) - mean * mean + 1e-5f);
            const float* gg = sel ? kg : qg;
            const float* bb = sel ? kb : qb;
            float sc = sel ? 1.f : 0.125f;
            p[lane]      = ((v0 - mean) * inv * gg[lane]      + bb[lane])      * sc;
            p[lane + 32] = ((v1 - mean) * inv * gg[lane + 32] + bb[lane + 32]) * sc;
        }
    }
    __syncthreads();

    const __half* bp = bias + (size_t)bh * BSLD;
    const float4* Q4 = (const float4*)Qs;
    const float4* K4 = (const float4*)Ks;
    for (int t = threadIdx.x; t < 17 * 17; t += 256) {
        int n0 = (t / 17) * 4, m0 = (t % 17) * 4;
        float acc[4][4] = {};
        #pragma unroll 4
        for (int d4 = 0; d4 < 16; d4++) {
            float4 qv[4], kv[4];
            #pragma unroll
            for (int i = 0; i < 4; i++) qv[i] = Q4[(n0 + i) * 16 + d4];
            #pragma unroll
            for (int j = 0; j < 4; j++) kv[j] = K4[(m0 + j) * 16 + d4];
            #pragma unroll
            for (int i = 0; i < 4; i++)
                #pragma unroll
                for (int j = 0; j < 4; j++) acc[i][j] += dot4(qv[i], kv[j]);
        }
        #pragma unroll
        for (int i = 0; i < 4; i++)
            #pragma unroll
            for (int j = 0; j < 4; j++) {
                int n = n0 + i, m = m0 + j;
                if (n < 65 && m < 65)
                    S[n * 66 + m] = acc[i][j] + __half2float(bp[n * 65 + m]);
            }
    }
    __syncthreads();

    for (int n = wid; n < 65; n += 8) {
        float* r = S + n * 66;
        float mx = -1e30f;
        for (int m = lane; m < 65; m += 32) mx = fmaxf(mx, r[m]);
        #pragma unroll
        for (int ofs = 16; ofs; ofs >>= 1) mx = fmaxf(mx, __shfl_xor_sync(~0u, mx, ofs));
        float sum = 0.f;
        for (int m = lane; m < 65; m += 32) { float e = __expf(r[m] - mx); r[m] = e; sum += e; }
        #pragma unroll
        for (int ofs = 16; ofs; ofs >>= 1) sum += __shfl_xor_sync(~0u, sum, ofs);
        float inv = 1.f / sum;
        for (int m = lane; m < 65; m += 32) r[m] *= inv;
    }
    __syncthreads();

    for (int t = threadIdx.x; t < 17 * 16; t += 256) {
        int n0 = (t / 16) * 4, d0 = (t % 16) * 4;
        float acc[4][4] = {};
        for (int m = 0; m < 65; m++) {
            float4 vv = *(const float4*)&Vs[m * 64 + d0];
            float sa[4];
            #pragma unroll
            for (int i = 0; i < 4; i++) sa[i] = S[(n0 + i) * 66 + m];
            #pragma unroll
            for (int i = 0; i < 4; i++) {
                acc[i][0] += sa[i] * vv.x; acc[i][1] += sa[i] * vv.y;
                acc[i][2] += sa[i] * vv.z; acc[i][3] += sa[i] * vv.w;
            }
        }
        #pragma unroll
        for (int i = 0; i < 4; i++)
            if (n0 + i < 65) {
                __half* op = o + (size_t)(b * N_ + n0 + i) * C_ + h * D_ + d0;
                *(__half2*)&op[0] = __floats2half2_rn(acc[i][0], acc[i][1]);
                *(__half2*)&op[2] = __floats2half2_rn(acc[i][2], acc[i][3]);
            }
    }
}

/* ---------------- host orchestration -------------------------------------- */
extern "C" void kernel_launch(void* const* d_in, const int* in_sizes, int n_in,
                              void* d_out, int out_size)
{
    (void)in_sizes; (void)n_in; (void)out_size;
    const float* x_in   = (const float*)d_in[0];
    const float* ln1_g  = (const float*)d_in[1];
    const float* ln1_b  = (const float*)d_in[2];
    const float* qkv_w  = (const float*)d_in[3];
    const float* proj_w = (const float*)d_in[4];
    const float* qn_g   = (const float*)d_in[5];
    const float* qn_b   = (const float*)d_in[6];
    const float* kn_g   = (const float*)d_in[7];
    const float* kn_b   = (const float*)d_in[8];
    const float* sg_w1  = (const float*)d_in[9];
    const float* sg1_g  = (const float*)d_in[10];
    const float* sg1_b  = (const float*)d_in[11];
    const float* sg_w2  = (const float*)d_in[12];
    const float* sg2_g  = (const float*)d_in[13];
    const float* sg2_b  = (const float*)d_in[14];
    const float* sgbw   = (const float*)d_in[15];
    const float* ln2_g  = (const float*)d_in[16];
    const float* ln2_b  = (const float*)d_in[17];
    const float* gate_w = (const float*)d_in[18];
    const float* val_w  = (const float*)d_in[19];
    const float* out_w  = (const float*)d_in[20];

    float *X, *C1f, *C2f;
    __half *Hh, *QKVh, *BIASh, *Oh, *C1h, *C2h, *MLPvh, *MLPh;
    __half *qkvT, *projT, *w1T, *w2T, *bwT, *valT, *gateT, *outT;
    cudaGetSymbolAddress((void**)&X,     g_x);
    cudaGetSymbolAddress((void**)&Hh,    g_hh);
    cudaGetSymbolAddress((void**)&QKVh,  g_qkvh);
    cudaGetSymbolAddress((void**)&BIASh, g_bsh);
    cudaGetSymbolAddress((void**)&Oh,    g_oh);
    cudaGetSymbolAddress((void**)&C1f,   g_c1f);
    cudaGetSymbolAddress((void**)&C1h,   g_c1h);
    cudaGetSymbolAddress((void**)&C2f,   g_c2f);
    cudaGetSymbolAddress((void**)&C2h,   g_c2h);
    cudaGetSymbolAddress((void**)&MLPvh, g_mlpvh);
    cudaGetSymbolAddress((void**)&MLPh,  g_mlph);
    cudaGetSymbolAddress((void**)&qkvT,  g_qkvT);
    cudaGetSymbolAddress((void**)&projT, g_projT);
    cudaGetSymbolAddress((void**)&w1T,   g_w1T);
    cudaGetSymbolAddress((void**)&w2T,   g_w2T);
    cudaGetSymbolAddress((void**)&bwT,   g_bwT);
    cudaGetSymbolAddress((void**)&valT,  g_valT);
    cudaGetSymbolAddress((void**)&gateT, g_gateT);
    cudaGetSymbolAddress((void**)&outT,  g_outT);

    cudaFuncSetAttribute(attn_kernel,
                         cudaFuncAttributeMaxDynamicSharedMemorySize, ATTN_SMEM);
    cudaFuncSetAttribute(gemm_h<0, false, false>,
                         cudaFuncAttributeMaxDynamicSharedMemorySize, GSMEM);
    cudaFuncSetAttribute(gemm_h<0, true, false>,
                         cudaFuncAttributeMaxDynamicSharedMemorySize, GSMEM);
    cudaFuncSetAttribute(gemm_h<1, false, false>,
                         cudaFuncAttributeMaxDynamicSharedMemorySize, GSMEM);
    cudaFuncSetAttribute(gemm_h<2, true, true>,
                         cudaFuncAttributeMaxDynamicSharedMemorySize, GSMEM);

    const dim3 tb(256);
    for (int l = 0; l < L_; l++) {
        const float* Xin = (l == 0) ? x_in : X;

        transpose_h<<<dim3(3 * C_ / 32, C_ / 32), tb>>>(
            qkv_w + (size_t)l * C_ * 3 * C_, 3 * C_, qkvT, C_, 3 * C_, 3 * C_);
        ln_kernel<false><<<BN_, tb>>>(Xin, Hh, ln1_g + l * C_, ln1_b + l * C_, C_);
        transpose_h<<<dim3(2 * LAT_ / 32, C_ / 32), tb>>>(
            sg_w1 + (size_t)l * C_ * 2 * LAT_, 2 * LAT_, w1T, C_, 2 * LAT_, 2 * LAT_);
        transpose_h<<<dim3(H_ * LAT_ / 32, 2 * LAT_ / 32), tb>>>(
            sg_w2 + (size_t)l * 2 * LAT_ * H_ * LAT_, H_ * LAT_, w2T, 2 * LAT_,
            H_ * LAT_, H_ * LAT_);
        transpose_h<<<dim3(BSLD / 32, LAT_ / 32), tb>>>(
            sgbw + (size_t)l * LAT_ * 4225, 4225, bwT, LAT_, 4225, BSLD);
        /* qkv = h @ qkv_w -> fp16  (33280 x 2304 x 768) */
        gemm_h<0, true, false><<<dim3(18, 260), tb, GSMEM>>>(Hh, C_, qkvT, C_,
            QKVh, 3 * C_, nullptr, C_);
        /* CLS MLP 1: (512 x 512 x 768), cls rows stride N*C */
        gemm_h<0, false, false><<<dim3(4, 4), tb, GSMEM>>>(Hh, N_ * C_, w1T, C_,
            C1f, 2 * LAT_, nullptr, C_);
        ln_kernel<true><<<B_, tb>>>(C1f, C1h,
            sg1_g + l * 2 * LAT_, sg1_b + l * 2 * LAT_, 2 * LAT_);
        /* CLS MLP 2: (512 x 3072 x 512) */
        gemm_h<0, false, false><<<dim3(24, 4), tb, GSMEM>>>(C1h, 2 * LAT_,
            w2T, 2 * LAT_, C2f, H_ * LAT_, nullptr, 2 * LAT_);
        ln_kernel<false><<<B_, tb>>>(C2f, C2h,
            sg2_g + l * H_ * LAT_, sg2_b + l * H_ * LAT_, H_ * LAT_);
        /* bias = lat2 @ bw -> fp16 : (6144 x 4352 x 256) */
        gemm_h<0, true, false><<<dim3(34, 48), tb, GSMEM>>>(C2h, LAT_, bwT, LAT_,
            BIASh, BSLD, nullptr, LAT_);
        /* fused attention -> fp16 O */
        attn_kernel<<<B_ * H_, tb, ATTN_SMEM>>>(QKVh, BIASh,
            qn_g + l * D_, qn_b + l * D_, kn_g + l * D_, kn_b + l * D_, Oh);
        transpose_h<<<dim3(C_ / 32, C_ / 32), tb>>>(
            proj_w + (size_t)l * C_ * C_, C_, projT, C_, C_, C_);
        /* x = Xin + o @ proj_w : (33280 x 768 x 768) */
        gemm_h<1, false, false><<<dim3(6, 260), tb, GSMEM>>>(Oh, C_, projT, C_,
            X, C_, Xin, C_);
        ln_kernel<false><<<BN_, tb>>>(X, Hh, ln2_g + l * C_, ln2_b + l * C_, C_);
        transpose_h<<<dim3(4 * C_ / 32, C_ / 32), tb>>>(
            val_w + (size_t)l * C_ * 4 * C_, 4 * C_, valT, C_, 4 * C_, 4 * C_);
        /* v = h2 @ vw -> fp16 */
        gemm_h<0, true, false><<<dim3(24, 260), tb, GSMEM>>>(Hh, C_, valT, C_,
            MLPvh, 4 * C_, nullptr, C_);
        transpose_h<<<dim3(4 * C_ / 32, C_ / 32), tb>>>(
            gate_w + (size_t)l * C_ * 4 * C_, 4 * C_, gateT, C_, 4 * C_, 4 * C_);
        /* gated = (h2 @ gw) * silu(v) -> fp16 */
        gemm_h<2, true, true><<<dim3(24, 260), tb, GSMEM>>>(Hh, C_, gateT, C_,
            MLPh, 4 * C_, MLPvh, C_);
        transpose_h<<<dim3(C_ / 32, 4 * C_ / 32), tb>>>(
            out_w + (size_t)l * 4 * C_ * C_, C_, outT, 4 * C_, C_, C_);
        /* x = x + gated @ ow : (33280 x 768 x 3072), last layer -> d_out */
        float* xo = (l == L_ - 1) ? (float*)d_out : X;
        gemm_h<1, false, false><<<dim3(6, 260), tb, GSMEM>>>(MLPh, 4 * C_,
            outT, 4 * C_, xo, C_, X, 4 * C_);
    }
}